// round 15
// baseline (speedup 1.0000x reference)
#include <cuda_runtime.h>
#include <cuda_bf16.h>
#include <math.h>
#include <stdint.h>

#define BB   8
#define SSEQ 4096
#define HD   768
#define CBLK 64
#define NBLK 64

// ---- device scratch ----
__device__ float g_a[BB*HD];
__device__ float g_t16[(size_t)BB*SSEQ*16];
__device__ __nv_bfloat16 g_xh[(size_t)BB*SSEQ*HD];
__device__ __nv_bfloat16 g_xl[(size_t)BB*SSEQ*HD];
__device__ __nv_bfloat16 g_Wth[3*HD*HD];
__device__ __nv_bfloat16 g_Wtl[3*HD*HD];
__device__ __nv_bfloat16 g_Qh[(size_t)BB*SSEQ*HD];
__device__ __nv_bfloat16 g_Ql[(size_t)BB*SSEQ*HD];
__device__ __nv_bfloat16 g_Kh[(size_t)BB*SSEQ*HD];
__device__ __nv_bfloat16 g_Kl[(size_t)BB*SSEQ*HD];
__device__ __nv_bfloat16 g_Vsh[(size_t)BB*SSEQ*HD];   // V * a^{-j_local}
__device__ __nv_bfloat16 g_Vsl[(size_t)BB*SSEQ*HD];
__device__ float g_T[(size_t)BB*7*HD*HD];
__device__ __nv_bfloat16 g_Sh[(size_t)BB*7*HD*HD];
__device__ __nv_bfloat16 g_Sl[(size_t)BB*7*HD*HD];
__device__ float g_apow[9*BB*HD];
__device__ float g_ainv[8*BB*HD];

__device__ __forceinline__ uint32_t smem_u32(const void* p) {
    uint32_t a;
    asm("{ .reg .u64 t; cvta.to.shared.u64 t, %1; cvt.u32.u64 %0, t; }"
        : "=r"(a) : "l"(p));
    return a;
}
__device__ __forceinline__ void ldsm_x4(uint32_t (&r)[4], uint32_t addr) {
    asm volatile("ldmatrix.sync.aligned.m8n8.x4.shared.b16 {%0,%1,%2,%3}, [%4];"
                 : "=r"(r[0]), "=r"(r[1]), "=r"(r[2]), "=r"(r[3]) : "r"(addr));
}
__device__ __forceinline__ void ldsm_x4_t(uint32_t (&r)[4], uint32_t addr) {
    asm volatile("ldmatrix.sync.aligned.m8n8.x4.trans.shared.b16 {%0,%1,%2,%3}, [%4];"
                 : "=r"(r[0]), "=r"(r[1]), "=r"(r[2]), "=r"(r[3]) : "r"(addr));
}
__device__ __forceinline__ void mma_bf16(float (&c)[4], const uint32_t a[4],
                                         const uint32_t b0, const uint32_t b1) {
    asm volatile(
        "mma.sync.aligned.m16n8k16.row.col.f32.bf16.bf16.f32 "
        "{%0,%1,%2,%3}, {%4,%5,%6,%7}, {%8,%9}, {%0,%1,%2,%3};"
        : "+f"(c[0]), "+f"(c[1]), "+f"(c[2]), "+f"(c[3])
        : "r"(a[0]), "r"(a[1]), "r"(a[2]), "r"(a[3]), "r"(b0), "r"(b1));
}
__device__ __forceinline__ void cpasync16(uint32_t sa, const void* gp) {
    asm volatile("cp.async.cg.shared.global [%0], [%1], 16;" :: "r"(sa), "l"(gp));
}
__device__ __forceinline__ __nv_bfloat162 split_hi(float v0, float v1,
                                                   __nv_bfloat162& lo) {
    __nv_bfloat16 h0 = __float2bfloat16(v0);
    __nv_bfloat16 h1 = __float2bfloat16(v1);
    lo.x = __float2bfloat16(v0 - __bfloat162float(h0));
    lo.y = __float2bfloat16(v1 - __bfloat162float(h1));
    __nv_bfloat162 hi; hi.x = h0; hi.y = h1;
    return hi;
}

// ================= conversions (zero_a folded in) =================
__global__ void convert_x_kernel(const float* __restrict__ x) {
    size_t gid0 = (size_t)blockIdx.x * blockDim.x + threadIdx.x;
    if (gid0 < BB * HD) g_a[gid0] = 0.0f;
    size_t n4 = (size_t)BB * SSEQ * HD / 4;
    for (size_t i = gid0; i < n4; i += (size_t)gridDim.x * blockDim.x) {
        float4 v = ((const float4*)x)[i];
        __nv_bfloat162 l0, l1;
        __nv_bfloat162 h0 = split_hi(v.x, v.y, l0);
        __nv_bfloat162 h1 = split_hi(v.z, v.w, l1);
        ((__nv_bfloat162*)g_xh)[2*i]   = h0;
        ((__nv_bfloat162*)g_xh)[2*i+1] = h1;
        ((__nv_bfloat162*)g_xl)[2*i]   = l0;
        ((__nv_bfloat162*)g_xl)[2*i+1] = l1;
    }
}

__global__ void convert_w_kernel(const float* __restrict__ Wq,
                                 const float* __restrict__ Wk,
                                 const float* __restrict__ Wv) {
    int w = blockIdx.z;
    const float* W = (w == 0) ? Wq : ((w == 1) ? Wk : Wv);
    __nv_bfloat16* th = g_Wth + (size_t)w * HD * HD;
    __nv_bfloat16* tl = g_Wtl + (size_t)w * HD * HD;
    for (int idx = blockIdx.x * 256 + threadIdx.x; idx < HD * HD; idx += gridDim.x * 256) {
        int k = idx / HD, n = idx % HD;
        float v = W[idx];
        __nv_bfloat16 hi = __float2bfloat16(v);
        __nv_bfloat16 lo = __float2bfloat16(v - __bfloat162float(hi));
        th[(size_t)n * HD + k] = hi;
        tl[(size_t)n * HD + k] = lo;
    }
}

// ================= gate pipeline =================
__global__ __launch_bounds__(256) void t16_kernel(const float* __restrict__ x,
                                                  const float* __restrict__ W1) {
    extern __shared__ char sm[];
    float* W1s = (float*)sm;   // [768][17]
    int t = threadIdx.x;
    for (int i = t; i < HD * 16; i += 256) {
        int r = i >> 4, c = i & 15;
        W1s[r * 17 + c] = W1[i];
    }
    __syncthreads();
    int w = t >> 5, lane = t & 31;
    int row = blockIdx.x * 8 + w;
    const float* xr = x + (size_t)row * HD;
    float tp[16];
#pragma unroll
    for (int j = 0; j < 16; j++) tp[j] = 0.0f;
    for (int i = lane; i < HD; i += 32) {
        float xv = xr[i];
        const float* w1r = &W1s[i * 17];
#pragma unroll
        for (int j = 0; j < 16; j++) tp[j] = fmaf(xv, w1r[j], tp[j]);
    }
#pragma unroll
    for (int off = 16; off > 0; off >>= 1)
#pragma unroll
        for (int j = 0; j < 16; j++)
            tp[j] += __shfl_xor_sync(0xffffffffu, tp[j], off);
    if (lane == 0) {
        float* op = g_t16 + (size_t)row * 16;
#pragma unroll
        for (int q = 0; q < 4; q++)
            ((float4*)op)[q] = make_float4(tp[q*4], tp[q*4+1], tp[q*4+2], tp[q*4+3]);
    }
}

__global__ __launch_bounds__(256) void sig_kernel(const float* __restrict__ W2,
                                                  const float* __restrict__ bvec) {
    extern __shared__ char sm[];
    float* W2s = (float*)sm;             // [16][768]
    float* tbuf = (float*)sm + 16 * HD;  // [64][16]
    int t = threadIdx.x;
    int b = blockIdx.y, sc0 = blockIdx.x * 64;
    for (int i = t; i < 16 * HD; i += 256) W2s[i] = W2[i];
    {
        const float* tp = g_t16 + ((size_t)b * SSEQ + sc0) * 16;
        for (int i = t; i < 64 * 16; i += 256) tbuf[i] = tp[i];
    }
    __syncthreads();

    int d0 = t, d1 = t + 256, d2 = t + 512;
    float bv0 = bvec[d0], bv1 = bvec[d1], bv2 = bvec[d2];
    float acc0 = 0.0f, acc1 = 0.0f, acc2 = 0.0f;
    for (int r = 0; r < 64; r++) {
        const float* tr = &tbuf[r * 16];
        float h0 = bv0, h1 = bv1, h2 = bv2;
#pragma unroll
        for (int j = 0; j < 16; j++) {
            float tv = tr[j];
            h0 = fmaf(tv, W2s[j * HD + d0], h0);
            h1 = fmaf(tv, W2s[j * HD + d1], h1);
            h2 = fmaf(tv, W2s[j * HD + d2], h2);
        }
        acc0 += __expf(-0.0625f * __logf(1.0f + __expf(-h0)));
        acc1 += __expf(-0.0625f * __logf(1.0f + __expf(-h1)));
        acc2 += __expf(-0.0625f * __logf(1.0f + __expf(-h2)));
    }
    const float inv = 1.0f / (float)SSEQ;
    atomicAdd(&g_a[b * HD + d0], acc0 * inv);
    atomicAdd(&g_a[b * HD + d1], acc1 * inv);
    atomicAdd(&g_a[b * HD + d2], acc2 * inv);
}

__global__ void powers_kernel() {
    int idx = blockIdx.x * blockDim.x + threadIdx.x;
    if (idx >= BB * HD) return;
    int b = idx / HD, d = idx % HD;
    float a = g_a[idx];
    float p = 1.0f;
#pragma unroll
    for (int q = 0; q <= 8; q++) { g_apow[((size_t)q * BB + b) * HD + d] = p; p *= a; }
    float ia = 1.0f / a, pv = 1.0f;
#pragma unroll
    for (int q = 0; q < 8; q++) { g_ainv[((size_t)q * BB + b) * HD + d] = pv; pv *= ia; }
}

// ================= QKV mma: 4 warps, 64x64 warp tile, k-chunk 48 ==========
#define QKV_KC 48
#define QKV_STRIDE 56            // 48 elems + 8 pad -> 112 B rows (16B multiple)
#define QKV_ARR_BYTES 14336      // 128 * 56 * 2
#define QKV_STAGE_BYTES 57344    // 4 arrays
#define QKV_SMEM 114688

__global__ __launch_bounds__(128, 2) void qkv_mma_kernel() {
    extern __shared__ char sm[];
    uint32_t smb = smem_u32(sm);
    int t = threadIdx.x, lane = t & 31, w = t >> 5;
    int wm = w & 1, wn = w >> 1;     // wm,wn in 0..1; warp tile 64x64
    int nb = blockIdx.x * 128;
    int mb = blockIdx.y * 128;
    int mat = blockIdx.z;
    const __nv_bfloat16* Bh_g = g_Wth + (size_t)mat * HD * HD;
    const __nv_bfloat16* Bl_g = g_Wtl + (size_t)mat * HD * HD;

    float acc[4][8][4];
#pragma unroll
    for (int i = 0; i < 4; i++)
#pragma unroll
        for (int j = 0; j < 8; j++)
#pragma unroll
            for (int q = 0; q < 4; q++) acc[i][j][q] = 0.0f;

    // 3072 16B chunks per stage, 24 per thread (128 threads)
    auto issue = [&](int s, int k0) {
#pragma unroll
        for (int q = 0; q < 24; q++) {
            int id = t + q * 128;
            int arr = id / 768, rem = id % 768;
            int row = rem / 6, c = (rem % 6) * 8;
            const __nv_bfloat16* gp;
            if (arr == 0)      gp = g_xh + (size_t)(mb + row) * HD + k0 + c;
            else if (arr == 1) gp = g_xl + (size_t)(mb + row) * HD + k0 + c;
            else if (arr == 2) gp = Bh_g + (size_t)(nb + row) * HD + k0 + c;
            else               gp = Bl_g + (size_t)(nb + row) * HD + k0 + c;
            uint32_t sa = smb + s * QKV_STAGE_BYTES + arr * QKV_ARR_BYTES
                        + (row * QKV_STRIDE + c) * 2;
            cpasync16(sa, gp);
        }
        asm volatile("cp.async.commit_group;");
    };

    issue(0, 0);

    int aRow = wm * 64 + (lane & 15);
    int aColSel = (lane >> 4) * 8;
    int bRow = wn * 64 + (lane & 7) + ((lane >> 4) << 3);
    int bColSel = ((lane >> 3) & 1) * 8;

    for (int it = 0; it < 16; it++) {
        int s = it & 1;
        if (it + 1 < 16) {
            issue(1 - s, (it + 1) * QKV_KC);
            asm volatile("cp.async.wait_group 1;");
        } else {
            asm volatile("cp.async.wait_group 0;");
        }
        __syncthreads();

        uint32_t stage = smb + s * QKV_STAGE_BYTES;
#pragma unroll
        for (int kk = 0; kk < 3; kk++) {
            int aCol = kk * 16 + aColSel;
            int bCol = kk * 16 + bColSel;
            uint32_t ah[4][4], al[4][4];
#pragma unroll
            for (int mf = 0; mf < 4; mf++) {
                uint32_t addr = stage + ((aRow + mf * 16) * QKV_STRIDE + aCol) * 2;
                ldsm_x4(ah[mf], addr);
                ldsm_x4(al[mf], addr + QKV_ARR_BYTES);
            }
            uint32_t bh[8][2], bl[8][2];
#pragma unroll
            for (int ng = 0; ng < 4; ng++) {
                uint32_t addr = stage + 2 * QKV_ARR_BYTES
                              + ((bRow + ng * 16) * QKV_STRIDE + bCol) * 2;
                uint32_t r[4];
                ldsm_x4(r, addr);
                bh[2*ng][0] = r[0]; bh[2*ng][1] = r[1];
                bh[2*ng+1][0] = r[2]; bh[2*ng+1][1] = r[3];
                ldsm_x4(r, addr + QKV_ARR_BYTES);
                bl[2*ng][0] = r[0]; bl[2*ng][1] = r[1];
                bl[2*ng+1][0] = r[2]; bl[2*ng+1][1] = r[3];
            }
#pragma unroll
            for (int mf = 0; mf < 4; mf++)
#pragma unroll
                for (int nf = 0; nf < 8; nf++) {
                    mma_bf16(acc[mf][nf], ah[mf], bh[nf][0], bh[nf][1]);
                    mma_bf16(acc[mf][nf], ah[mf], bl[nf][0], bl[nf][1]);
                    mma_bf16(acc[mf][nf], al[mf], bh[nf][0], bh[nf][1]);
                }
        }
        __syncthreads();
    }

    int g = lane >> 2, tig = lane & 3;
    if (mat < 2) {
        __nv_bfloat16* Oh = (mat == 0) ? g_Qh : g_Kh;
        __nv_bfloat16* Ol = (mat == 0) ? g_Ql : g_Kl;
#pragma unroll
        for (int mf = 0; mf < 4; mf++)
#pragma unroll
            for (int half = 0; half < 2; half++) {
                size_t grow = (size_t)(mb + wm * 64 + mf * 16 + g + half * 8);
#pragma unroll
                for (int nf = 0; nf < 8; nf++) {
                    int col = nb + wn * 64 + nf * 8 + tig * 2;
                    __nv_bfloat162 lo;
                    __nv_bfloat162 hi = split_hi(acc[mf][nf][half*2],
                                                 acc[mf][nf][half*2+1], lo);
                    *(__nv_bfloat162*)&Oh[grow * HD + col] = hi;
                    *(__nv_bfloat162*)&Ol[grow * HD + col] = lo;
                }
            }
    } else {
#pragma unroll
        for (int mf = 0; mf < 4; mf++)
#pragma unroll
            for (int half = 0; half < 2; half++) {
                int grow = mb + wm * 64 + mf * 16 + g + half * 8;
                int b = grow >> 12;
                int j = ((grow & 4095) >> 6) & 7;
                const float* ai = g_ainv + ((size_t)j * BB + b) * HD + nb + wn * 64;
#pragma unroll
                for (int nf = 0; nf < 8; nf++) {
                    int co = nf * 8 + tig * 2;
                    float2 av = *(const float2*)(ai + co);
                    float v0 = acc[mf][nf][half*2]     * av.x;
                    float v1 = acc[mf][nf][half*2 + 1] * av.y;
                    __nv_bfloat162 lo;
                    __nv_bfloat162 hi = split_hi(v0, v1, lo);
                    size_t off = (size_t)grow * HD + nb + wn * 64 + co;
                    *(__nv_bfloat162*)&g_Vsh[off] = hi;
                    *(__nv_bfloat162*)&g_Vsl[off] = lo;
                }
            }
    }
}

// ================= diag-block attention on tensor cores =================
#define AT_QSTRIDE 72
#define AT_ARR     9216
#define AT_STAGE   36864
#define AT_PF_OFF  73728
#define AT_M2_OFF  90624
#define AT_VARR    17408
#define AT_SMEM    109056

__global__ __launch_bounds__(256) void attn_mma_kernel(float* __restrict__ out) {
    extern __shared__ char sm[];
    uint32_t smb = smem_u32(sm);
    int t = threadIdx.x, lane = t & 31, w = t >> 5;
    int wm = w & 1, wn = w >> 1;
    int nb = blockIdx.x, b = blockIdx.y;
    int jloc = nb & 7;
    size_t row0 = (size_t)b * SSEQ + (size_t)nb * 64;
    int gr = lane >> 2, tig = lane & 3;

    float pacc[2][2][4];
#pragma unroll
    for (int i = 0; i < 2; i++)
#pragma unroll
        for (int q = 0; q < 2; q++)
#pragma unroll
            for (int e = 0; e < 4; e++) pacc[i][q][e] = 0.0f;

    auto issue1 = [&](int s, int kc) {
#pragma unroll
        for (int q = 0; q < 8; q++) {
            int id = t + q * 256;
            int arr = id >> 9, rem = id & 511;
            int row = rem >> 3, cc = (rem & 7) * 8;
            const __nv_bfloat16* gp;
            if (arr == 0)      gp = g_Qh + (row0 + row) * HD + kc * 64 + cc;
            else if (arr == 1) gp = g_Ql + (row0 + row) * HD + kc * 64 + cc;
            else if (arr == 2) gp = g_Kh + (row0 + row) * HD + kc * 64 + cc;
            else               gp = g_Kl + (row0 + row) * HD + kc * 64 + cc;
            cpasync16(smb + s * AT_STAGE + arr * AT_ARR + (row * AT_QSTRIDE + cc) * 2, gp);
        }
        asm volatile("cp.async.commit_group;");
    };

    issue1(0, 0);
    for (int kc = 0; kc < 12; kc++) {
        int s = kc & 1;
        if (kc + 1 < 12) {
            issue1(1 - s, kc + 1);
            asm volatile("cp.async.wait_group 1;");
        } else {
            asm volatile("cp.async.wait_group 0;");
        }
        __syncthreads();
        uint32_t stg = smb + s * AT_STAGE;
#pragma unroll
        for (int kk = 0; kk < 4; kk++) {
            uint32_t ah[2][4], al[2][4];
#pragma unroll
            for (int mf = 0; mf < 2; mf++) {
                uint32_t addr = stg + ((wm * 32 + mf * 16 + (lane & 15)) * AT_QSTRIDE
                              + kk * 16 + (lane >> 4) * 8) * 2;
                ldsm_x4(ah[mf], addr);
                ldsm_x4(al[mf], addr + AT_ARR);
            }
            uint32_t bh[2][2], bl[2][2];
            {
                uint32_t addr = stg + 2 * AT_ARR
                              + ((wn * 16 + (lane & 7) + ((lane >> 4) << 3)) * AT_QSTRIDE
                              + kk * 16 + ((lane >> 3) & 1) * 8) * 2;
                uint32_t r[4];
                ldsm_x4(r, addr);
                bh[0][0] = r[0]; bh[0][1] = r[1]; bh[1][0] = r[2]; bh[1][1] = r[3];
                ldsm_x4(r, addr + AT_ARR);
                bl[0][0] = r[0]; bl[0][1] = r[1]; bl[1][0] = r[2]; bl[1][1] = r[3];
            }
#pragma unroll
            for (int mf = 0; mf < 2; mf++)
#pragma unroll
                for (int nf = 0; nf < 2; nf++) {
                    mma_bf16(pacc[mf][nf], ah[mf], bh[nf][0], bh[nf][1]);
                    mma_bf16(pacc[mf][nf], ah[mf], bl[nf][0], bl[nf][1]);
                    mma_bf16(pacc[mf][nf], al[mf], bh[nf][0], bh[nf][1]);
                }
        }
        __syncthreads();
    }

    float* PfP = (float*)(sm + AT_PF_OFF);
#pragma unroll
    for (int mf = 0; mf < 2; mf++)
#pragma unroll
        for (int nf = 0; nf < 2; nf++) {
            int row = wm * 32 + mf * 16 + gr;
            int col = wn * 16 + nf * 8 + tig * 2;
            PfP[row * 66 + col]       = pacc[mf][nf][0];
            PfP[row * 66 + col + 1]   = pacc[mf][nf][1];
            PfP[(row + 8) * 66 + col]     = pacc[mf][nf][2];
            PfP[(row + 8) * 66 + col + 1] = pacc[mf][nf][3];
        }
    __syncthreads();

    {
        __nv_bfloat16* M2h = (__nv_bfloat16*)(sm + AT_M2_OFF);
        __nv_bfloat16* M2l = (__nv_bfloat16*)(sm + AT_M2_OFF + AT_ARR);
        const float scale = 1.0f / 27.712813f;
#pragma unroll
        for (int r8 = 0; r8 < 8; r8++) {
            int r = w * 8 + r8;
            float p0 = PfP[r * 66 + lane], p1 = PfP[r * 66 + lane + 32];
            float s0 = (lane <= r)        ? p0 * scale : 0.0f;
            float s1 = ((lane + 32) <= r) ? p1 * scale : 0.0f;
            float m = fmaxf(s0, s1);
#pragma unroll
            for (int off = 16; off; off >>= 1)
                m = fmaxf(m, __shfl_xor_sync(0xffffffffu, m, off));
            float e0 = expf(s0 - m), e1 = expf(s1 - m);
            float ssum = e0 + e1;
#pragma unroll
            for (int off = 16; off; off >>= 1)
                ssum += __shfl_xor_sync(0xffffffffu, ssum, off);
            float invz = 1.0f / ssum;
            float v0 = p0 + e0 * invz;
            float v1 = p1 + e1 * invz;
            __nv_bfloat16 h0 = __float2bfloat16(v0);
            __nv_bfloat16 h1 = __float2bfloat16(v1);
            M2h[r * AT_QSTRIDE + lane]      = h0;
            M2h[r * AT_QSTRIDE + lane + 32] = h1;
            M2l[r * AT_QSTRIDE + lane]      = __float2bfloat16(v0 - __bfloat162float(h0));
            M2l[r * AT_QSTRIDE + lane + 32] = __float2bfloat16(v1 - __bfloat162float(h1));
        }
    }
    __syncthreads();

    auto issue2 = [&](int s, int dt) {
#pragma unroll
        for (int q = 0; q < 8; q++) {
            int id = t + q * 256;
            int arr = id >> 10, rem = id & 1023;
            int row = rem >> 4, cc = (rem & 15) * 8;
            const __nv_bfloat16* gp = (arr == 0)
                ? g_Vsh + (row0 + row) * HD + dt * 128 + cc
                : g_Vsl + (row0 + row) * HD + dt * 128 + cc;
            cpasync16(smb + s * (2 * AT_VARR) + arr * AT_VARR + (row * 136 + cc) * 2, gp);
        }
        asm volatile("cp.async.commit_group;");
    };

    issue2(0, 0);
    const float* aj = g_apow + ((size_t)jloc * BB + b) * HD;
    for (int dt = 0; dt < 6; dt++) {
        int s = dt & 1;
        if (dt + 1 < 6) {
            issue2(1 - s, dt + 1);
            asm volatile("cp.async.wait_group 1;");
        } else {
            asm volatile("cp.async.wait_group 0;");
        }
        __syncthreads();

        float oacc[2][4][4];
#pragma unroll
        for (int i = 0; i < 2; i++)
#pragma unroll
            for (int q = 0; q < 4; q++)
#pragma unroll
                for (int e = 0; e < 4; e++) oacc[i][q][e] = 0.0f;

#pragma unroll
        for (int kk = 0; kk < 4; kk++) {
            uint32_t ah[2][4], al[2][4];
#pragma unroll
            for (int mf = 0; mf < 2; mf++) {
                uint32_t addr = smb + AT_M2_OFF
                              + ((wm * 32 + mf * 16 + (lane & 15)) * AT_QSTRIDE
                              + kk * 16 + (lane >> 4) * 8) * 2;
                ldsm_x4(ah[mf], addr);
                ldsm_x4(al[mf], addr + AT_ARR);
            }
            uint32_t bh[4][2], bl[4][2];
#pragma unroll
            for (int ng = 0; ng < 2; ng++) {
                uint32_t addr = smb + s * (2 * AT_VARR)
                              + ((kk * 16 + ((lane >> 3) & 1) * 8 + (lane & 7)) * 136
                              + wn * 32 + ng * 16 + (lane >> 4) * 8) * 2;
                uint32_t r[4];
                ldsm_x4_t(r, addr);
                bh[2*ng][0] = r[0]; bh[2*ng][1] = r[1];
                bh[2*ng+1][0] = r[2]; bh[2*ng+1][1] = r[3];
                ldsm_x4_t(r, addr + AT_VARR);
                bl[2*ng][0] = r[0]; bl[2*ng][1] = r[1];
                bl[2*ng+1][0] = r[2]; bl[2*ng+1][1] = r[3];
            }
#pragma unroll
            for (int mf = 0; mf < 2; mf++)
#pragma unroll
                for (int nf = 0; nf < 4; nf++) {
                    mma_bf16(oacc[mf][nf], ah[mf], bh[nf][0], bh[nf][1]);
                    mma_bf16(oacc[mf][nf], ah[mf], bl[nf][0], bl[nf][1]);
                    mma_bf16(oacc[mf][nf], al[mf], bh[nf][0], bh[nf][1]);
                }
        }
#pragma unroll
        for (int mf = 0; mf < 2; mf++) {
            size_t row = row0 + wm * 32 + mf * 16 + gr;
#pragma unroll
            for (int nf = 0; nf < 4; nf++) {
                int col = dt * 128 + wn * 32 + nf * 8 + tig * 2;
                float s0 = aj[col], s1 = aj[col + 1];
                *(float2*)&out[row * HD + col] =
                    make_float2(oacc[mf][nf][0] * s0, oacc[mf][nf][1] * s1);
                *(float2*)&out[(row + 8) * HD + col] =
                    make_float2(oacc[mf][nf][2] * s0, oacc[mf][nf][3] * s1);
            }
        }
        __syncthreads();
    }
}

// ================= chunk totals (triple-buffered) =================
#define CT_STRIDE 136
#define CT_ARR_BYTES 8704
#define CT_STAGE_BYTES 34816
#define CT_SMEM 104448

__global__ __launch_bounds__(256, 2) void chunk_total_kernel() {
    extern __shared__ char sm[];
    uint32_t smb = smem_u32(sm);
    int t = threadIdx.x, lane = t & 31, w = t >> 5;
    int wm = w & 1, wn = w >> 1;
    int tile = blockIdx.x;
    int m0 = (tile % 6) * 128;
    int n0 = (tile / 6) * 128;
    int bg = blockIdx.y;
    int b = bg / 7, g = bg % 7;
    size_t crow0 = (size_t)b * SSEQ + (size_t)g * 512;

    float acc[4][4][4];
#pragma unroll
    for (int i = 0; i < 4; i++)
#pragma unroll
        for (int j = 0; j < 4; j++)
#pragma unroll
            for (int q = 0; q < 4; q++) acc[i][j][q] = 0.0f;

    auto issue = [&](int s, int k0) {
#pragma unroll
        for (int q = 0; q < 8; q++) {
            int id = t + q * 256;
            int arr = id >> 9, rem = id & 511;
            int row = rem >> 4, c = (rem & 15) * 8;
            const __nv_bfloat16* gp;
            size_t go = (crow0 + k0 + row) * HD;
            if (arr == 0)      gp = g_Vsh + go + m0 + c;
            else if (arr == 1) gp = g_Vsl + go + m0 + c;
            else if (arr == 2) gp = g_Kh  + go + n0 + c;
            else               gp = g_Kl  + go + n0 + c;
            uint32_t sa = smb + s * CT_STAGE_BYTES + arr * CT_ARR_BYTES
                        + (row * CT_STRIDE + c) * 2;
            cpasync16(sa, gp);
        }
        asm volatile("cp.async.commit_group;");
    };

    issue(0, 0);
    issue(1, 32);

    int aMem_r = ((lane >> 4) << 3) + (lane & 7);
    int aMem_c = wm * 64 + ((lane >> 3) & 1) * 8;
    int bMem_r = ((lane >> 3) & 1) * 8 + (lane & 7);
    int bMem_c = wn * 32 + (lane >> 4) * 8;

    for (int it = 0; it < 16; it++) {
        int s = it % 3;
        if (it + 2 < 16) {
            issue((it + 2) % 3, (it + 2) * 32);
            asm volatile("cp.async.wait_group 2;");
        } else if (it + 1 < 16) {
            asm volatile("cp.async.wait_group 1;");
        } else {
            asm volatile("cp.async.wait_group 0;");
        }
        __syncthreads();

        uint32_t stage = smb + s * CT_STAGE_BYTES;
#pragma unroll
        for (int kk = 0; kk < 2; kk++) {
            uint32_t ah[4][4], al[4][4];
#pragma unroll
            for (int mf = 0; mf < 4; mf++) {
                uint32_t addr = stage + ((kk * 16 + aMem_r) * CT_STRIDE
                              + aMem_c + mf * 16) * 2;
                ldsm_x4_t(ah[mf], addr);
                ldsm_x4_t(al[mf], addr + CT_ARR_BYTES);
            }
            uint32_t bh[4][2], bl[4][2];
#pragma unroll
            for (int ng = 0; ng < 2; ng++) {
                uint32_t addr = stage + 2 * CT_ARR_BYTES
                              + ((kk * 16 + bMem_r) * CT_STRIDE + bMem_c + ng * 16) * 2;
                uint32_t r[4];
                ldsm_x4_t(r, addr);
                bh[2*ng][0] = r[0]; bh[2*ng][1] = r[1];
                bh[2*ng+1][0] = r[2]; bh[2*ng+1][1] = r[3];
                ldsm_x4_t(r, addr + CT_ARR_BYTES);
                bl[2*ng][0] = r[0]; bl[2*ng][1] = r[1];
                bl[2*ng+1][0] = r[2]; bl[2*ng+1][1] = r[3];
            }
#pragma unroll
            for (int mf = 0; mf < 4; mf++)
#pragma unroll
                for (int nf = 0; nf < 4; nf++) {
                    mma_bf16(acc[mf][nf], ah[mf], bh[nf][0], bh[nf][1]);
                    mma_bf16(acc[mf][nf], ah[mf], bl[nf][0], bl[nf][1]);
                    mma_bf16(acc[mf][nf], al[mf], bh[nf][0], bh[nf][1]);
                }
        }
        __syncthreads();
    }

    int gr = lane >> 2, tig = lane & 3;
    float* Tp = g_T + (size_t)bg * HD * HD;
    const float* a7 = g_apow + ((size_t)7 * BB + b) * HD;
#pragma unroll
    for (int mf = 0; mf < 4; mf++) {
        int d0r = m0 + wm * 64 + mf * 16 + gr;
        float s0 = a7[d0r], s1 = a7[d0r + 8];
#pragma unroll
        for (int nf = 0; nf < 4; nf++) {
            int col = n0 + wn * 32 + nf * 8 + tig * 2;
            float* p0 = Tp + (size_t)d0r * HD + col;
            float* p1 = Tp + (size_t)(d0r + 8) * HD + col;
            *(float2*)p0 = make_float2(acc[mf][nf][0] * s0, acc[mf][nf][1] * s0);
            *(float2*)p1 = make_float2(acc[mf][nf][2] * s1, acc[mf][nf][3] * s1);
        }
    }
}

// ================= sequential scan (vectorized x4) =================
__global__ __launch_bounds__(256) void scan_kernel() {
    int b = blockIdx.y;
    int idx = blockIdx.x * 256 + threadIdx.x;
    int d = idx / (HD / 4), h4 = (idx % (HD / 4)) * 4;
    float a8 = g_apow[((size_t)8 * BB + b) * HD + d];
    float4 carry = make_float4(0.f, 0.f, 0.f, 0.f);
    size_t base = ((size_t)b * 7) * HD * HD + (size_t)d * HD + h4;
#pragma unroll
    for (int g = 0; g < 7; g++) {
        float4 tv = *(const float4*)&g_T[base + (size_t)g * HD * HD];
        carry.x = fmaf(a8, carry.x, tv.x);
        carry.y = fmaf(a8, carry.y, tv.y);
        carry.z = fmaf(a8, carry.z, tv.z);
        carry.w = fmaf(a8, carry.w, tv.w);
        __nv_bfloat162 l0, l1;
        __nv_bfloat162 h0 = split_hi(carry.x, carry.y, l0);
        __nv_bfloat162 h1 = split_hi(carry.z, carry.w, l1);
        size_t o = base + (size_t)g * HD * HD;
        *(__nv_bfloat162*)&g_Sh[o]     = h0;
        *(__nv_bfloat162*)&g_Sh[o + 2] = h1;
        *(__nv_bfloat162*)&g_Sl[o]     = l0;
        *(__nv_bfloat162*)&g_Sl[o + 2] = l1;
    }
}

// ================= inter-chunk (k-chunk 48, unchanged 256-thread) ==========
#define IT_STRIDE 56
#define IT_ARR_BYTES 14336
#define IT_STAGE_BYTES 57344
#define IT_SMEM 114688

__global__ __launch_bounds__(256, 2) void inter_kernel(float* __restrict__ out) {
    extern __shared__ char sm[];
    uint32_t smb = smem_u32(sm);
    int t = threadIdx.x, lane = t & 31, w = t >> 5;
    int wm = w & 1, wn = w >> 1;
    int nb = blockIdx.x * 128;
    int mb = blockIdx.y * 128;
    int combo = blockIdx.z;
    int b = combo / 7, gm1 = combo % 7, g = gm1 + 1;
    size_t arow0 = (size_t)b * SSEQ + (size_t)g * 512 + mb;
    size_t srow0 = ((size_t)b * 7 + gm1) * HD * HD;

    float acc[4][4][4];
#pragma unroll
    for (int i = 0; i < 4; i++)
#pragma unroll
        for (int j = 0; j < 4; j++)
#pragma unroll
            for (int q = 0; q < 4; q++) acc[i][j][q] = 0.0f;

    auto issue = [&](int s, int k0) {
#pragma unroll
        for (int q = 0; q < 12; q++) {
            int id = t + q * 256;
            int arr = id / 768, rem = id % 768;
            int row = rem / 6, c = (rem % 6) * 8;
            const __nv_bfloat16* gp;
            if (arr == 0)      gp = g_Qh + (arow0 + row) * HD + k0 + c;
            else if (arr == 1) gp = g_Ql + (arow0 + row) * HD + k0 + c;
            else if (arr == 2) gp = g_Sh + srow0 + (size_t)(nb + row) * HD + k0 + c;
            else               gp = g_Sl + srow0 + (size_t)(nb + row) * HD + k0 + c;
            uint32_t sa = smb + s * IT_STAGE_BYTES + arr * IT_ARR_BYTES
                        + (row * IT_STRIDE + c) * 2;
            cpasync16(sa, gp);
        }
        asm volatile("cp.async.commit_group;");
    };

    issue(0, 0);

    int aRow = wm * 64 + (lane & 15);
    int aColSel = (lane >> 4) * 8;
    int bRow = wn * 32 + (lane & 7) + ((lane >> 4) << 3);
    int bColSel = ((lane >> 3) & 1) * 8;

    for (int it = 0; it < 16; it++) {
        int s = it & 1;
        if (it + 1 < 16) {
            issue(1 - s, (it + 1) * QKV_KC);
            asm volatile("cp.async.wait_group 1;");
        } else {
            asm volatile("cp.async.wait_group 0;");
        }
        __syncthreads();

        uint32_t stage = smb + s * IT_STAGE_BYTES;
#pragma unroll
        for (int kk = 0; kk < 3; kk++) {
            int aCol = kk * 16 + aColSel;
            int bCol = kk * 16 + bColSel;
            uint32_t ah[4][4], al[4][4];
#pragma unroll
            for (int mf = 0; mf < 4; mf++) {
                uint32_t addr = stage + ((aRow + mf * 16) * IT_STRIDE + aCol) * 2;
                ldsm_x4(ah[mf], addr);
                ldsm_x4(al[mf], addr + IT_ARR_BYTES);
            }
            uint32_t bh[4][2], bl[4][2];
#pragma unroll
            for (int ng = 0; ng < 2; ng++) {
                uint32_t addr = stage + 2 * IT_ARR_BYTES
                              + ((bRow + ng * 16) * IT_STRIDE + bCol) * 2;
                uint32_t r[4];
                ldsm_x4(r, addr);
                bh[2*ng][0] = r[0]; bh[2*ng][1] = r[1];
                bh[2*ng+1][0] = r[2]; bh[2*ng+1][1] = r[3];
                ldsm_x4(r, addr + IT_ARR_BYTES);
                bl[2*ng][0] = r[0]; bl[2*ng][1] = r[1];
                bl[2*ng+1][0] = r[2]; bl[2*ng+1][1] = r[3];
            }
#pragma unroll
            for (int mf = 0; mf < 4; mf++)
#pragma unroll
                for (int nf = 0; nf < 4; nf++) {
                    mma_bf16(acc[mf][nf], ah[mf], bh[nf][0], bh[nf][1]);
                    mma_bf16(acc[mf][nf], ah[mf], bl[nf][0], bl[nf][1]);
                    mma_bf16(acc[mf][nf], al[mf], bh[nf][0], bh[nf][1]);
                }
        }
        __syncthreads();
    }

    int gr = lane >> 2, tig = lane & 3;
    int p = blockIdx.y * 2 + wm + 1;
    const float* sc = g_apow + ((size_t)p * BB + b) * HD;
#pragma unroll
    for (int mf = 0; mf < 4; mf++) {
        size_t row = arow0 + wm * 64 + mf * 16 + gr;
#pragma unroll
        for (int nf = 0; nf < 4; nf++) {
            int col = nb + wn * 32 + nf * 8 + tig * 2;
            float s0 = sc[col], s1 = sc[col + 1];
            float* p0 = out + row * HD + col;
            float* p1 = out + (row + 8) * HD + col;
            float2 v0 = *(float2*)p0, v1 = *(float2*)p1;
            v0.x += acc[mf][nf][0] * s0; v0.y += acc[mf][nf][1] * s1;
            v1.x += acc[mf][nf][2] * s0; v1.y += acc[mf][nf][3] * s1;
            *(float2*)p0 = v0; *(float2*)p1 = v1;
        }
    }
}

// ================= intra-chunk cross-block (heavy-first order) =================
#define IN_PSTRIDE 456
#define IN_PBYTES  58368
#define IN_STG     116736
#define IN_S1ARR   9216
#define IN_S1STAGE 36864
#define IN_S2ARR   17408
#define IN_S2STAGE 34816
#define IN_SMEM    190464

__global__ __launch_bounds__(256) void intra_kernel(float* __restrict__ out) {
    extern __shared__ char sm[];
    uint32_t smb = smem_u32(sm);
    uint32_t Ph = smb, Pl = smb + IN_PBYTES, STG = smb + IN_STG;
    int t = threadIdx.x, lane = t & 31, w = t >> 5;
    int wm = w & 1, wn = w >> 1;
    int tt = 7 - blockIdx.x;            // heavy blocks launch first
    int g = blockIdx.y, b = blockIdx.z;
    size_t qrow0 = (size_t)b * SSEQ + (size_t)(g * 8 + tt) * 64;
    size_t krow0 = (size_t)b * SSEQ + (size_t)g * 512;
    int gr = lane >> 2, tig = lane & 3;

    auto issue1 = [&](int s, int j, int kc) {
#pragma unroll
        for (int q = 0; q < 8; q++) {
            int id = t + q * 256;
            int arr = id >> 9, rem = id & 511;
            int row = rem >> 3, cc = (rem & 7) * 8;
            const __nv_bfloat16* gp;
            if (arr == 0)      gp = g_Qh + (qrow0 + row) * HD + kc * 64 + cc;
            else if (arr == 1) gp = g_Ql + (qrow0 + row) * HD + kc * 64 + cc;
            else if (arr == 2) gp = g_Kh + (krow0 + j * 64 + row) * HD + kc * 64 + cc;
            else               gp = g_Kl + (krow0 + j * 64 + row) * HD + kc * 64 + cc;
            cpasync16(STG + s * IN_S1STAGE + arr * IN_S1ARR + (row * 72 + cc) * 2, gp);
        }
        asm volatile("cp.async.commit_group;");
    };

    float pacc[2][2][4];
    int total1 = tt * 12;
    issue1(0, 0, 0);
    for (int it = 0; it < total1; it++) {
        int s = it & 1;
        int kc = it % 12;
        if (kc == 0) {
#pragma unroll
            for (int i = 0; i < 2; i++)
#pragma unroll
                for (int q = 0; q < 2; q++)
#pragma unroll
                    for (int e = 0; e < 4; e++) pacc[i][q][e] = 0.0f;
        }
        if (it + 1 < total1) {
            issue1(1 - s, (it + 1) / 12, (it + 1) % 12);
            asm volatile("cp.async.wait_group 1;");
        } else {
            asm volatile("cp.async.wait_group 0;");
        }
        __syncthreads();

        uint32_t stg = STG + s * IN_S1STAGE;
#pragma unroll
        for (int kk = 0; kk < 4; kk++) {
            uint32_t ah[2][4], al[2][4];
#pragma unroll
            for (int mf = 0; mf < 2; mf++) {
                uint32_t addr = stg + ((wm * 32 + mf * 16 + (lane & 15)) * 72
                              + kk * 16 + (lane >> 4) * 8) * 2;
                ldsm_x4(ah[mf], addr);
                ldsm_x4(al[mf], addr + IN_S1ARR);
            }
            uint32_t bh[2][2], bl[2][2];
            {
                uint32_t addr = stg + 2 * IN_S1ARR
                              + ((wn * 16 + (lane & 7) + ((lane >> 4) << 3)) * 72
                              + kk * 16 + ((lane >> 3) & 1) * 8) * 2;
                uint32_t r[4];
                ldsm_x4(r, addr);
                bh[0][0] = r[0]; bh[0][1] = r[1]; bh[1][0] = r[2]; bh[1][1] = r[3];
                ldsm_x4(r, addr + IN_S1ARR);
                bl[0][0] = r[0]; bl[0][1] = r[1]; bl[1][0] = r[2]; bl[1][1] = r[3];
            }
#pragma unroll
            for (int mf = 0; mf < 2; mf++)
#pragma unroll
                for (int nf = 0; nf < 2; nf++) {
                    mma_bf16(pacc[mf][nf], ah[mf], bh[nf][0], bh[nf][1]);
                    mma_bf16(pacc[mf][nf], ah[mf], bl[nf][0], bl[nf][1]);
                    mma_bf16(pacc[mf][nf], al[mf], bh[nf][0], bh[nf][1]);
                }
        }

        if (kc == 11) {
            int j = it / 12;
#pragma unroll
            for (int mf = 0; mf < 2; mf++)
#pragma unroll
                for (int nf = 0; nf < 2; nf++) {
                    int row = wm * 32 + mf * 16 + gr;
                    int col = j * 64 + wn * 16 + nf * 8 + tig * 2;
#pragma unroll
                    for (int half = 0; half < 2; half++) {
                        __nv_bfloat162 lp;
                        __nv_bfloat162 hp = split_hi(pacc[mf][nf][half*2],
                                                     pacc[mf][nf][half*2+1], lp);
                        uint32_t off = ((row + half * 8) * IN_PSTRIDE + col) * 2;
                        *(__nv_bfloat162*)(sm + (Ph - smb) + off) = hp;
                        *(__nv_bfloat162*)(sm + (Pl - smb) + off) = lp;
                    }
                }
        }
        __syncthreads();
    }

    auto issue2 = [&](int s, int dt, int ec) {
#pragma unroll
        for (int q = 0; q < 8; q++) {
            int id = t + q * 256;
            int arr = id >> 10, rem = id & 1023;
            int row = rem >> 4, cc = (rem & 15) * 8;
            const __nv_bfloat16* gp = (arr == 0)
                ? g_Vsh + (krow0 + ec * 64 + row) * HD + dt * 128 + cc
                : g_Vsl + (krow0 + ec * 64 + row) * HD + dt * 128 + cc;
            cpasync16(STG + s * IN_S2STAGE + arr * IN_S2ARR + (row * 136 + cc) * 2, gp);
        }
        asm volatile("cp.async.commit_group;");
    };

    const float* sc = g_apow + ((size_t)tt * BB + b) * HD;
    float oacc[2][4][4];
    int total2 = 6 * tt;
    issue2(0, 0, 0);
    for (int it = 0; it < total2; it++) {
        int s = it & 1;
        int dt = it / tt, ec = it % tt;
        if (ec == 0) {
#pragma unroll
            for (int i = 0; i < 2; i++)
#pragma unroll
                for (int q = 0; q < 4; q++)
#pragma unroll
                    for (int e = 0; e < 4; e++) oacc[i][q][e] = 0.0f;
        }
        if (it + 1 < total2) {
            issue2(1 - s, (it + 1) / tt, (it + 1) % tt);
            asm volatile("cp.async.wait_group 1;");
        } else {
            asm volatile("cp.async.wait_group 0;");
        }
        __syncthreads();

        uint32_t stg = STG + s * IN_S2STAGE;
#pragma unroll
        for (int kk = 0; kk < 4; kk++) {
            uint32_t ah[2][4], al[2][4];
#pragma unroll
            for (int mf = 0; mf < 2; mf++) {
                uint32_t addr = Ph + ((wm * 32 + mf * 16 + (lane & 15)) * IN_PSTRIDE
                              + ec * 64 + kk * 16 + (lane >> 4) * 8) * 2;
                ldsm_x4(ah[mf], addr);
                ldsm_x4(al[mf], addr + IN_PBYTES);
            }
            uint32_t bh[4][2], bl[4][2];
#pragma unroll
            for (int ng = 0; ng < 2; ng++) {
                uint32_t addr = stg + ((kk * 16 + ((lane >> 3) & 1) * 8 + (lane & 7)) * 136
                              + wn * 32 + ng * 16 + (lane >> 4) * 8) * 2;
                uint32_t r[4];
                ldsm_x4_t(r, addr);
                bh[2*ng][0] = r[0]; bh[2*ng][1] = r[1];
                bh[2*ng+1][0] = r[2]; bh[2*ng+1][1] = r[3];
                ldsm_x4_t(r, addr + IN_S2ARR);
                bl[2*ng][0] = r[0]; bl[2*ng][1] = r[1];
                bl[2*ng+1][0] = r[2]; bl[2*ng+1][1] = r[3];
            }
#pragma unroll
            for (int mf = 0; mf < 2; mf++)
#pragma unroll
                for (int nf = 0; nf < 4; nf++) {
                    mma_bf16(oacc[mf][nf], ah[mf], bh[nf][0], bh[nf][1]);
                    mma_bf16(oacc[mf][nf], al[mf], bh[nf][0], bh[nf][1]);
                    mma_bf16(oacc[mf][nf], ah[mf], bl[nf][0], bl[nf][1]);
                }
        }

        if (ec == tt - 1) {
#pragma unroll
            for (int mf = 0; mf < 2; mf++) {
                size_t row = qrow0 + wm * 32 + mf * 16 + gr;
#pragma unroll
                for (int nf = 0; nf < 4; nf++) {
                    int col = dt * 128 + wn * 32 + nf * 8 + tig * 2;
                    float s0 = sc[col], s1 = sc[col + 1];
                    float* p0 = out + row * HD + col;
                    float* p1 = out + (row + 8) * HD + col;
                    float2 v0 = *(float2*)p0, v1 = *(float2*)p1;
                    v0.x += oacc[mf][nf][0] * s0; v0.y += oacc[mf][nf][1] * s1;
                    v1.x += oacc[mf][nf][2] * s0; v1.y += oacc[mf][nf][3] * s1;
                    *(float2*)p0 = v0; *(float2*)p1 = v1;
                }
            }
        }
        __syncthreads();
    }
}

// ================= launch =================
extern "C" void kernel_launch(void* const* d_in, const int* in_sizes, int n_in,
                              void* d_out, int out_size)
{
    const float* x  = (const float*)d_in[0];
    const float* Wq = (const float*)d_in[1];
    const float* Wk = (const float*)d_in[2];
    const float* Wv = (const float*)d_in[3];
    const float* W1 = (const float*)d_in[4];
    const float* W2 = (const float*)d_in[5];
    const float* bv = (const float*)d_in[6];
    float* out = (float*)d_out;

    cudaFuncSetAttribute((const void*)qkv_mma_kernel,
                         cudaFuncAttributeMaxDynamicSharedMemorySize, QKV_SMEM);
    cudaFuncSetAttribute((const void*)inter_kernel,
                         cudaFuncAttributeMaxDynamicSharedMemorySize, IT_SMEM);
    cudaFuncSetAttribute((const void*)chunk_total_kernel,
                         cudaFuncAttributeMaxDynamicSharedMemorySize, CT_SMEM);
    cudaFuncSetAttribute((const void*)intra_kernel,
                         cudaFuncAttributeMaxDynamicSharedMemorySize, IN_SMEM);
    cudaFuncSetAttribute((const void*)attn_mma_kernel,
                         cudaFuncAttributeMaxDynamicSharedMemorySize, AT_SMEM);
    cudaFuncSetAttribute((const void*)t16_kernel,
                         cudaFuncAttributeMaxDynamicSharedMemorySize, 52224);
    cudaFuncSetAttribute((const void*)sig_kernel,
                         cudaFuncAttributeMaxDynamicSharedMemorySize, 53248);

    convert_x_kernel<<<6144, 256>>>(x);
    convert_w_kernel<<<dim3(64, 1, 3), 256>>>(Wq, Wk, Wv);
    t16_kernel<<<4096, 256, 52224>>>(x, W1);
    sig_kernel<<<dim3(64, BB), 256, 53248>>>(W2, bv);
    powers_kernel<<<24, 256>>>();

    qkv_mma_kernel<<<dim3(6, 256, 3), 128, QKV_SMEM>>>();

    attn_mma_kernel<<<dim3(NBLK, BB), 256, AT_SMEM>>>(out);

    chunk_total_kernel<<<dim3(36, 56), 256, CT_SMEM>>>();
    scan_kernel<<<dim3(576, BB), 256>>>();
    inter_kernel<<<dim3(6, 4, 56), 256, IT_SMEM>>>(out);
    intra_kernel<<<dim3(7, 8, 8), 256, IN_SMEM>>>(out);
}

// round 16
// speedup vs baseline: 1.5102x; 1.5102x over previous
#include <cuda_runtime.h>
#include <cuda_bf16.h>
#include <math.h>
#include <stdint.h>

#define BB   8
#define SSEQ 4096
#define HD   768
#define CBLK 64
#define NBLK 64

// ---- device scratch ----
__device__ float g_a[BB*HD];
__device__ float g_t16[(size_t)BB*SSEQ*16];
__device__ __nv_bfloat16 g_xh[(size_t)BB*SSEQ*HD];
__device__ __nv_bfloat16 g_xl[(size_t)BB*SSEQ*HD];
__device__ __nv_bfloat16 g_Wth[3*HD*HD];
__device__ __nv_bfloat16 g_Wtl[3*HD*HD];
__device__ __nv_bfloat16 g_Qh[(size_t)BB*SSEQ*HD];
__device__ __nv_bfloat16 g_Ql[(size_t)BB*SSEQ*HD];
__device__ __nv_bfloat16 g_Kh[(size_t)BB*SSEQ*HD];
__device__ __nv_bfloat16 g_Kl[(size_t)BB*SSEQ*HD];
__device__ __nv_bfloat16 g_Vsh[(size_t)BB*SSEQ*HD];   // V * a^{-j_local}
__device__ __nv_bfloat16 g_Vsl[(size_t)BB*SSEQ*HD];
__device__ float g_T[(size_t)BB*7*HD*HD];
__device__ __nv_bfloat16 g_Sh[(size_t)BB*7*HD*HD];
__device__ __nv_bfloat16 g_Sl[(size_t)BB*7*HD*HD];
__device__ float g_apow[9*BB*HD];
__device__ float g_ainv[8*BB*HD];

__device__ __forceinline__ uint32_t smem_u32(const void* p) {
    uint32_t a;
    asm("{ .reg .u64 t; cvta.to.shared.u64 t, %1; cvt.u32.u64 %0, t; }"
        : "=r"(a) : "l"(p));
    return a;
}
__device__ __forceinline__ void ldsm_x4(uint32_t (&r)[4], uint32_t addr) {
    asm volatile("ldmatrix.sync.aligned.m8n8.x4.shared.b16 {%0,%1,%2,%3}, [%4];"
                 : "=r"(r[0]), "=r"(r[1]), "=r"(r[2]), "=r"(r[3]) : "r"(addr));
}
__device__ __forceinline__ void ldsm_x4_t(uint32_t (&r)[4], uint32_t addr) {
    asm volatile("ldmatrix.sync.aligned.m8n8.x4.trans.shared.b16 {%0,%1,%2,%3}, [%4];"
                 : "=r"(r[0]), "=r"(r[1]), "=r"(r[2]), "=r"(r[3]) : "r"(addr));
}
__device__ __forceinline__ void mma_bf16(float (&c)[4], const uint32_t a[4],
                                         const uint32_t b0, const uint32_t b1) {
    asm volatile(
        "mma.sync.aligned.m16n8k16.row.col.f32.bf16.bf16.f32 "
        "{%0,%1,%2,%3}, {%4,%5,%6,%7}, {%8,%9}, {%0,%1,%2,%3};"
        : "+f"(c[0]), "+f"(c[1]), "+f"(c[2]), "+f"(c[3])
        : "r"(a[0]), "r"(a[1]), "r"(a[2]), "r"(a[3]), "r"(b0), "r"(b1));
}
__device__ __forceinline__ void cpasync16(uint32_t sa, const void* gp) {
    asm volatile("cp.async.cg.shared.global [%0], [%1], 16;" :: "r"(sa), "l"(gp));
}
__device__ __forceinline__ __nv_bfloat162 split_hi(float v0, float v1,
                                                   __nv_bfloat162& lo) {
    __nv_bfloat16 h0 = __float2bfloat16(v0);
    __nv_bfloat16 h1 = __float2bfloat16(v1);
    lo.x = __float2bfloat16(v0 - __bfloat162float(h0));
    lo.y = __float2bfloat16(v1 - __bfloat162float(h1));
    __nv_bfloat162 hi; hi.x = h0; hi.y = h1;
    return hi;
}

// ================= conversions (zero_a folded in) =================
__global__ void convert_x_kernel(const float* __restrict__ x) {
    size_t gid0 = (size_t)blockIdx.x * blockDim.x + threadIdx.x;
    if (gid0 < BB * HD) g_a[gid0] = 0.0f;
    size_t n4 = (size_t)BB * SSEQ * HD / 4;
    for (size_t i = gid0; i < n4; i += (size_t)gridDim.x * blockDim.x) {
        float4 v = ((const float4*)x)[i];
        __nv_bfloat162 l0, l1;
        __nv_bfloat162 h0 = split_hi(v.x, v.y, l0);
        __nv_bfloat162 h1 = split_hi(v.z, v.w, l1);
        ((__nv_bfloat162*)g_xh)[2*i]   = h0;
        ((__nv_bfloat162*)g_xh)[2*i+1] = h1;
        ((__nv_bfloat162*)g_xl)[2*i]   = l0;
        ((__nv_bfloat162*)g_xl)[2*i+1] = l1;
    }
}

__global__ void convert_w_kernel(const float* __restrict__ Wq,
                                 const float* __restrict__ Wk,
                                 const float* __restrict__ Wv) {
    int w = blockIdx.z;
    const float* W = (w == 0) ? Wq : ((w == 1) ? Wk : Wv);
    __nv_bfloat16* th = g_Wth + (size_t)w * HD * HD;
    __nv_bfloat16* tl = g_Wtl + (size_t)w * HD * HD;
    for (int idx = blockIdx.x * 256 + threadIdx.x; idx < HD * HD; idx += gridDim.x * 256) {
        int k = idx / HD, n = idx % HD;
        float v = W[idx];
        __nv_bfloat16 hi = __float2bfloat16(v);
        __nv_bfloat16 lo = __float2bfloat16(v - __bfloat162float(hi));
        th[(size_t)n * HD + k] = hi;
        tl[(size_t)n * HD + k] = lo;
    }
}

// ================= gate pipeline =================
__global__ __launch_bounds__(256) void t16_kernel(const float* __restrict__ x,
                                                  const float* __restrict__ W1) {
    extern __shared__ char sm[];
    float* W1s = (float*)sm;   // [768][17]
    int t = threadIdx.x;
    for (int i = t; i < HD * 16; i += 256) {
        int r = i >> 4, c = i & 15;
        W1s[r * 17 + c] = W1[i];
    }
    __syncthreads();
    int w = t >> 5, lane = t & 31;
    int row = blockIdx.x * 8 + w;
    const float* xr = x + (size_t)row * HD;
    float tp[16];
#pragma unroll
    for (int j = 0; j < 16; j++) tp[j] = 0.0f;
    for (int i = lane; i < HD; i += 32) {
        float xv = xr[i];
        const float* w1r = &W1s[i * 17];
#pragma unroll
        for (int j = 0; j < 16; j++) tp[j] = fmaf(xv, w1r[j], tp[j]);
    }
#pragma unroll
    for (int off = 16; off > 0; off >>= 1)
#pragma unroll
        for (int j = 0; j < 16; j++)
            tp[j] += __shfl_xor_sync(0xffffffffu, tp[j], off);
    if (lane == 0) {
        float* op = g_t16 + (size_t)row * 16;
#pragma unroll
        for (int q = 0; q < 4; q++)
            ((float4*)op)[q] = make_float4(tp[q*4], tp[q*4+1], tp[q*4+2], tp[q*4+3]);
    }
}

__global__ __launch_bounds__(256) void sig_kernel(const float* __restrict__ W2,
                                                  const float* __restrict__ bvec) {
    extern __shared__ char sm[];
    float* W2s = (float*)sm;             // [16][768]
    float* tbuf = (float*)sm + 16 * HD;  // [64][16]
    int t = threadIdx.x;
    int b = blockIdx.y, sc0 = blockIdx.x * 64;
    for (int i = t; i < 16 * HD; i += 256) W2s[i] = W2[i];
    {
        const float* tp = g_t16 + ((size_t)b * SSEQ + sc0) * 16;
        for (int i = t; i < 64 * 16; i += 256) tbuf[i] = tp[i];
    }
    __syncthreads();

    int d0 = t, d1 = t + 256, d2 = t + 512;
    float bv0 = bvec[d0], bv1 = bvec[d1], bv2 = bvec[d2];
    float acc0 = 0.0f, acc1 = 0.0f, acc2 = 0.0f;
    for (int r = 0; r < 64; r++) {
        const float* tr = &tbuf[r * 16];
        float h0 = bv0, h1 = bv1, h2 = bv2;
#pragma unroll
        for (int j = 0; j < 16; j++) {
            float tv = tr[j];
            h0 = fmaf(tv, W2s[j * HD + d0], h0);
            h1 = fmaf(tv, W2s[j * HD + d1], h1);
            h2 = fmaf(tv, W2s[j * HD + d2], h2);
        }
        acc0 += __expf(-0.0625f * __logf(1.0f + __expf(-h0)));
        acc1 += __expf(-0.0625f * __logf(1.0f + __expf(-h1)));
        acc2 += __expf(-0.0625f * __logf(1.0f + __expf(-h2)));
    }
    const float inv = 1.0f / (float)SSEQ;
    atomicAdd(&g_a[b * HD + d0], acc0 * inv);
    atomicAdd(&g_a[b * HD + d1], acc1 * inv);
    atomicAdd(&g_a[b * HD + d2], acc2 * inv);
}

__global__ void powers_kernel() {
    int idx = blockIdx.x * blockDim.x + threadIdx.x;
    if (idx >= BB * HD) return;
    int b = idx / HD, d = idx % HD;
    float a = g_a[idx];
    float p = 1.0f;
#pragma unroll
    for (int q = 0; q <= 8; q++) { g_apow[((size_t)q * BB + b) * HD + d] = p; p *= a; }
    float ia = 1.0f / a, pv = 1.0f;
#pragma unroll
    for (int q = 0; q < 8; q++) { g_ainv[((size_t)q * BB + b) * HD + d] = pv; pv *= ia; }
}

// ================= QKV mma, k-chunk 48 (16B-aligned stride 56) ==========
#define QKV_KC 48
#define QKV_STRIDE 56            // 48 elems + 8 pad -> 112 B rows (16B multiple)
#define QKV_ARR_BYTES 14336      // 128 * 56 * 2
#define QKV_STAGE_BYTES 57344    // 4 arrays
#define QKV_SMEM 114688

__global__ __launch_bounds__(256, 2) void qkv_mma_kernel() {
    extern __shared__ char sm[];
    uint32_t smb = smem_u32(sm);
    int t = threadIdx.x, lane = t & 31, w = t >> 5;
    int wm = w & 1, wn = w >> 1;
    int nb = blockIdx.x * 128;
    int mb = blockIdx.y * 128;
    int mat = blockIdx.z;
    const __nv_bfloat16* Bh_g = g_Wth + (size_t)mat * HD * HD;
    const __nv_bfloat16* Bl_g = g_Wtl + (size_t)mat * HD * HD;

    float acc[4][4][4];
#pragma unroll
    for (int i = 0; i < 4; i++)
#pragma unroll
        for (int j = 0; j < 4; j++)
#pragma unroll
            for (int q = 0; q < 4; q++) acc[i][j][q] = 0.0f;

    // 3072 16B chunks per stage (128 rows x 6 chunks x 4 arrays), 12/thread
    auto issue = [&](int s, int k0) {
#pragma unroll
        for (int q = 0; q < 12; q++) {
            int id = t + q * 256;
            int arr = id / 768, rem = id % 768;
            int row = rem / 6, c = (rem % 6) * 8;
            const __nv_bfloat16* gp;
            if (arr == 0)      gp = g_xh + (size_t)(mb + row) * HD + k0 + c;
            else if (arr == 1) gp = g_xl + (size_t)(mb + row) * HD + k0 + c;
            else if (arr == 2) gp = Bh_g + (size_t)(nb + row) * HD + k0 + c;
            else               gp = Bl_g + (size_t)(nb + row) * HD + k0 + c;
            uint32_t sa = smb + s * QKV_STAGE_BYTES + arr * QKV_ARR_BYTES
                        + (row * QKV_STRIDE + c) * 2;
            cpasync16(sa, gp);
        }
        asm volatile("cp.async.commit_group;");
    };

    issue(0, 0);

    int aRow = wm * 64 + (lane & 15);
    int aColSel = (lane >> 4) * 8;
    int bRow = wn * 32 + (lane & 7) + ((lane >> 4) << 3);
    int bColSel = ((lane >> 3) & 1) * 8;

    for (int it = 0; it < 16; it++) {
        int s = it & 1;
        if (it + 1 < 16) {
            issue(1 - s, (it + 1) * QKV_KC);
            asm volatile("cp.async.wait_group 1;");
        } else {
            asm volatile("cp.async.wait_group 0;");
        }
        __syncthreads();

        uint32_t stage = smb + s * QKV_STAGE_BYTES;
#pragma unroll
        for (int kk = 0; kk < 3; kk++) {
            int aCol = kk * 16 + aColSel;
            int bCol = kk * 16 + bColSel;
            uint32_t ah[4][4], al[4][4];
#pragma unroll
            for (int mf = 0; mf < 4; mf++) {
                uint32_t addr = stage + ((aRow + mf * 16) * QKV_STRIDE + aCol) * 2;
                ldsm_x4(ah[mf], addr);
                ldsm_x4(al[mf], addr + QKV_ARR_BYTES);
            }
            uint32_t bh[4][2], bl[4][2];
#pragma unroll
            for (int ng = 0; ng < 2; ng++) {
                uint32_t addr = stage + 2 * QKV_ARR_BYTES
                              + ((bRow + ng * 16) * QKV_STRIDE + bCol) * 2;
                uint32_t r[4];
                ldsm_x4(r, addr);
                bh[2*ng][0] = r[0]; bh[2*ng][1] = r[1];
                bh[2*ng+1][0] = r[2]; bh[2*ng+1][1] = r[3];
                ldsm_x4(r, addr + QKV_ARR_BYTES);
                bl[2*ng][0] = r[0]; bl[2*ng][1] = r[1];
                bl[2*ng+1][0] = r[2]; bl[2*ng+1][1] = r[3];
            }
#pragma unroll
            for (int mf = 0; mf < 4; mf++)
#pragma unroll
                for (int nf = 0; nf < 4; nf++) {
                    mma_bf16(acc[mf][nf], ah[mf], bh[nf][0], bh[nf][1]);
                    mma_bf16(acc[mf][nf], ah[mf], bl[nf][0], bl[nf][1]);
                    mma_bf16(acc[mf][nf], al[mf], bh[nf][0], bh[nf][1]);
                }
        }
        __syncthreads();
    }

    // fused epilogue: split hi/lo (V also scaled by a^{-j}); uniform branch on mat
    int g = lane >> 2, tig = lane & 3;
    if (mat < 2) {
        __nv_bfloat16* Oh = (mat == 0) ? g_Qh : g_Kh;
        __nv_bfloat16* Ol = (mat == 0) ? g_Ql : g_Kl;
#pragma unroll
        for (int mf = 0; mf < 4; mf++)
#pragma unroll
            for (int half = 0; half < 2; half++) {
                size_t grow = (size_t)(mb + wm * 64 + mf * 16 + g + half * 8);
#pragma unroll
                for (int nf = 0; nf < 4; nf++) {
                    int col = nb + wn * 32 + nf * 8 + tig * 2;
                    __nv_bfloat162 lo;
                    __nv_bfloat162 hi = split_hi(acc[mf][nf][half*2],
                                                 acc[mf][nf][half*2+1], lo);
                    *(__nv_bfloat162*)&Oh[grow * HD + col] = hi;
                    *(__nv_bfloat162*)&Ol[grow * HD + col] = lo;
                }
            }
    } else {
#pragma unroll
        for (int mf = 0; mf < 4; mf++)
#pragma unroll
            for (int half = 0; half < 2; half++) {
                int grow = mb + wm * 64 + mf * 16 + g + half * 8;
                int b = grow >> 12;
                int j = ((grow & 4095) >> 6) & 7;
                const float* ai = g_ainv + ((size_t)j * BB + b) * HD + nb + wn * 32;
#pragma unroll
                for (int nf = 0; nf < 4; nf++) {
                    int co = nf * 8 + tig * 2;
                    float2 av = *(const float2*)(ai + co);
                    float v0 = acc[mf][nf][half*2]     * av.x;
                    float v1 = acc[mf][nf][half*2 + 1] * av.y;
                    __nv_bfloat162 lo;
                    __nv_bfloat162 hi = split_hi(v0, v1, lo);
                    size_t off = (size_t)grow * HD + nb + wn * 32 + co;
                    *(__nv_bfloat162*)&g_Vsh[off] = hi;
                    *(__nv_bfloat162*)&g_Vsl[off] = lo;
                }
            }
    }
}

// ================= diag-block attention on tensor cores =================
#define AT_QSTRIDE 72
#define AT_ARR     9216
#define AT_STAGE   36864
#define AT_PF_OFF  73728
#define AT_M2_OFF  90624
#define AT_VARR    17408
#define AT_SMEM    109056

__global__ __launch_bounds__(256) void attn_mma_kernel(float* __restrict__ out) {
    extern __shared__ char sm[];
    uint32_t smb = smem_u32(sm);
    int t = threadIdx.x, lane = t & 31, w = t >> 5;
    int wm = w & 1, wn = w >> 1;
    int nb = blockIdx.x, b = blockIdx.y;
    int jloc = nb & 7;
    size_t row0 = (size_t)b * SSEQ + (size_t)nb * 64;
    int gr = lane >> 2, tig = lane & 3;

    float pacc[2][2][4];
#pragma unroll
    for (int i = 0; i < 2; i++)
#pragma unroll
        for (int q = 0; q < 2; q++)
#pragma unroll
            for (int e = 0; e < 4; e++) pacc[i][q][e] = 0.0f;

    auto issue1 = [&](int s, int kc) {
#pragma unroll
        for (int q = 0; q < 8; q++) {
            int id = t + q * 256;
            int arr = id >> 9, rem = id & 511;
            int row = rem >> 3, cc = (rem & 7) * 8;
            const __nv_bfloat16* gp;
            if (arr == 0)      gp = g_Qh + (row0 + row) * HD + kc * 64 + cc;
            else if (arr == 1) gp = g_Ql + (row0 + row) * HD + kc * 64 + cc;
            else if (arr == 2) gp = g_Kh + (row0 + row) * HD + kc * 64 + cc;
            else               gp = g_Kl + (row0 + row) * HD + kc * 64 + cc;
            cpasync16(smb + s * AT_STAGE + arr * AT_ARR + (row * AT_QSTRIDE + cc) * 2, gp);
        }
        asm volatile("cp.async.commit_group;");
    };

    issue1(0, 0);
    for (int kc = 0; kc < 12; kc++) {
        int s = kc & 1;
        if (kc + 1 < 12) {
            issue1(1 - s, kc + 1);
            asm volatile("cp.async.wait_group 1;");
        } else {
            asm volatile("cp.async.wait_group 0;");
        }
        __syncthreads();
        uint32_t stg = smb + s * AT_STAGE;
#pragma unroll
        for (int kk = 0; kk < 4; kk++) {
            uint32_t ah[2][4], al[2][4];
#pragma unroll
            for (int mf = 0; mf < 2; mf++) {
                uint32_t addr = stg + ((wm * 32 + mf * 16 + (lane & 15)) * AT_QSTRIDE
                              + kk * 16 + (lane >> 4) * 8) * 2;
                ldsm_x4(ah[mf], addr);
                ldsm_x4(al[mf], addr + AT_ARR);
            }
            uint32_t bh[2][2], bl[2][2];
            {
                uint32_t addr = stg + 2 * AT_ARR
                              + ((wn * 16 + (lane & 7) + ((lane >> 4) << 3)) * AT_QSTRIDE
                              + kk * 16 + ((lane >> 3) & 1) * 8) * 2;
                uint32_t r[4];
                ldsm_x4(r, addr);
                bh[0][0] = r[0]; bh[0][1] = r[1]; bh[1][0] = r[2]; bh[1][1] = r[3];
                ldsm_x4(r, addr + AT_ARR);
                bl[0][0] = r[0]; bl[0][1] = r[1]; bl[1][0] = r[2]; bl[1][1] = r[3];
            }
#pragma unroll
            for (int mf = 0; mf < 2; mf++)
#pragma unroll
                for (int nf = 0; nf < 2; nf++) {
                    mma_bf16(pacc[mf][nf], ah[mf], bh[nf][0], bh[nf][1]);
                    mma_bf16(pacc[mf][nf], ah[mf], bl[nf][0], bl[nf][1]);
                    mma_bf16(pacc[mf][nf], al[mf], bh[nf][0], bh[nf][1]);
                }
        }
        __syncthreads();
    }

    float* PfP = (float*)(sm + AT_PF_OFF);
#pragma unroll
    for (int mf = 0; mf < 2; mf++)
#pragma unroll
        for (int nf = 0; nf < 2; nf++) {
            int row = wm * 32 + mf * 16 + gr;
            int col = wn * 16 + nf * 8 + tig * 2;
            PfP[row * 66 + col]       = pacc[mf][nf][0];
            PfP[row * 66 + col + 1]   = pacc[mf][nf][1];
            PfP[(row + 8) * 66 + col]     = pacc[mf][nf][2];
            PfP[(row + 8) * 66 + col + 1] = pacc[mf][nf][3];
        }
    __syncthreads();

    {
        __nv_bfloat16* M2h = (__nv_bfloat16*)(sm + AT_M2_OFF);
        __nv_bfloat16* M2l = (__nv_bfloat16*)(sm + AT_M2_OFF + AT_ARR);
        const float scale = 1.0f / 27.712813f;
#pragma unroll
        for (int r8 = 0; r8 < 8; r8++) {
            int r = w * 8 + r8;
            float p0 = PfP[r * 66 + lane], p1 = PfP[r * 66 + lane + 32];
            float s0 = (lane <= r)        ? p0 * scale : 0.0f;
            float s1 = ((lane + 32) <= r) ? p1 * scale : 0.0f;
            float m = fmaxf(s0, s1);
#pragma unroll
            for (int off = 16; off; off >>= 1)
                m = fmaxf(m, __shfl_xor_sync(0xffffffffu, m, off));
            float e0 = expf(s0 - m), e1 = expf(s1 - m);
            float ssum = e0 + e1;
#pragma unroll
            for (int off = 16; off; off >>= 1)
                ssum += __shfl_xor_sync(0xffffffffu, ssum, off);
            float invz = 1.0f / ssum;
            float v0 = p0 + e0 * invz;
            float v1 = p1 + e1 * invz;
            __nv_bfloat16 h0 = __float2bfloat16(v0);
            __nv_bfloat16 h1 = __float2bfloat16(v1);
            M2h[r * AT_QSTRIDE + lane]      = h0;
            M2h[r * AT_QSTRIDE + lane + 32] = h1;
            M2l[r * AT_QSTRIDE + lane]      = __float2bfloat16(v0 - __bfloat162float(h0));
            M2l[r * AT_QSTRIDE + lane + 32] = __float2bfloat16(v1 - __bfloat162float(h1));
        }
    }
    __syncthreads();

    auto issue2 = [&](int s, int dt) {
#pragma unroll
        for (int q = 0; q < 8; q++) {
            int id = t + q * 256;
            int arr = id >> 10, rem = id & 1023;
            int row = rem >> 4, cc = (rem & 15) * 8;
            const __nv_bfloat16* gp = (arr == 0)
                ? g_Vsh + (row0 + row) * HD + dt * 128 + cc
                : g_Vsl + (row0 + row) * HD + dt * 128 + cc;
            cpasync16(smb + s * (2 * AT_VARR) + arr * AT_VARR + (row * 136 + cc) * 2, gp);
        }
        asm volatile("cp.async.commit_group;");
    };

    issue2(0, 0);
    const float* aj = g_apow + ((size_t)jloc * BB + b) * HD;
    for (int dt = 0; dt < 6; dt++) {
        int s = dt & 1;
        if (dt + 1 < 6) {
            issue2(1 - s, dt + 1);
            asm volatile("cp.async.wait_group 1;");
        } else {
            asm volatile("cp.async.wait_group 0;");
        }
        __syncthreads();

        float oacc[2][4][4];
#pragma unroll
        for (int i = 0; i < 2; i++)
#pragma unroll
            for (int q = 0; q < 4; q++)
#pragma unroll
                for (int e = 0; e < 4; e++) oacc[i][q][e] = 0.0f;

#pragma unroll
        for (int kk = 0; kk < 4; kk++) {
            uint32_t ah[2][4], al[2][4];
#pragma unroll
            for (int mf = 0; mf < 2; mf++) {
                uint32_t addr = smb + AT_M2_OFF
                              + ((wm * 32 + mf * 16 + (lane & 15)) * AT_QSTRIDE
                              + kk * 16 + (lane >> 4) * 8) * 2;
                ldsm_x4(ah[mf], addr);
                ldsm_x4(al[mf], addr + AT_ARR);
            }
            uint32_t bh[4][2], bl[4][2];
#pragma unroll
            for (int ng = 0; ng < 2; ng++) {
                uint32_t addr = smb + s * (2 * AT_VARR)
                              + ((kk * 16 + ((lane >> 3) & 1) * 8 + (lane & 7)) * 136
                              + wn * 32 + ng * 16 + (lane >> 4) * 8) * 2;
                uint32_t r[4];
                ldsm_x4_t(r, addr);
                bh[2*ng][0] = r[0]; bh[2*ng][1] = r[1];
                bh[2*ng+1][0] = r[2]; bh[2*ng+1][1] = r[3];
                ldsm_x4_t(r, addr + AT_VARR);
                bl[2*ng][0] = r[0]; bl[2*ng][1] = r[1];
                bl[2*ng+1][0] = r[2]; bl[2*ng+1][1] = r[3];
            }
#pragma unroll
            for (int mf = 0; mf < 2; mf++)
#pragma unroll
                for (int nf = 0; nf < 4; nf++) {
                    mma_bf16(oacc[mf][nf], ah[mf], bh[nf][0], bh[nf][1]);
                    mma_bf16(oacc[mf][nf], ah[mf], bl[nf][0], bl[nf][1]);
                    mma_bf16(oacc[mf][nf], al[mf], bh[nf][0], bh[nf][1]);
                }
        }
#pragma unroll
        for (int mf = 0; mf < 2; mf++) {
            size_t row = row0 + wm * 32 + mf * 16 + gr;
#pragma unroll
            for (int nf = 0; nf < 4; nf++) {
                int col = dt * 128 + wn * 32 + nf * 8 + tig * 2;
                float s0 = aj[col], s1 = aj[col + 1];
                *(float2*)&out[row * HD + col] =
                    make_float2(oacc[mf][nf][0] * s0, oacc[mf][nf][1] * s1);
                *(float2*)&out[(row + 8) * HD + col] =
                    make_float2(oacc[mf][nf][2] * s0, oacc[mf][nf][3] * s1);
            }
        }
        __syncthreads();
    }
}

// ================= chunk totals =================
#define CT_STRIDE 136
#define CT_ARR_BYTES 8704
#define CT_STAGE_BYTES 34816

__global__ __launch_bounds__(256) void chunk_total_kernel() {
    extern __shared__ char sm[];
    uint32_t smb = smem_u32(sm);
    int t = threadIdx.x, lane = t & 31, w = t >> 5;
    int wm = w & 1, wn = w >> 1;
    int tile = blockIdx.x;
    int m0 = (tile % 6) * 128;
    int n0 = (tile / 6) * 128;
    int bg = blockIdx.y;
    int b = bg / 7, g = bg % 7;
    size_t crow0 = (size_t)b * SSEQ + (size_t)g * 512;

    float acc[4][4][4];
#pragma unroll
    for (int i = 0; i < 4; i++)
#pragma unroll
        for (int j = 0; j < 4; j++)
#pragma unroll
            for (int q = 0; q < 4; q++) acc[i][j][q] = 0.0f;

    auto issue = [&](int s, int k0) {
#pragma unroll
        for (int q = 0; q < 8; q++) {
            int id = t + q * 256;
            int arr = id >> 9, rem = id & 511;
            int row = rem >> 4, c = (rem & 15) * 8;
            const __nv_bfloat16* gp;
            size_t go = (crow0 + k0 + row) * HD;
            if (arr == 0)      gp = g_Vsh + go + m0 + c;
            else if (arr == 1) gp = g_Vsl + go + m0 + c;
            else if (arr == 2) gp = g_Kh  + go + n0 + c;
            else               gp = g_Kl  + go + n0 + c;
            uint32_t sa = smb + s * CT_STAGE_BYTES + arr * CT_ARR_BYTES
                        + (row * CT_STRIDE + c) * 2;
            cpasync16(sa, gp);
        }
        asm volatile("cp.async.commit_group;");
    };

    issue(0, 0);

    int aMem_r = ((lane >> 4) << 3) + (lane & 7);
    int aMem_c = wm * 64 + ((lane >> 3) & 1) * 8;
    int bMem_r = ((lane >> 3) & 1) * 8 + (lane & 7);
    int bMem_c = wn * 32 + (lane >> 4) * 8;

    for (int it = 0; it < 16; it++) {
        int s = it & 1;
        if (it + 1 < 16) {
            issue(1 - s, (it + 1) * 32);
            asm volatile("cp.async.wait_group 1;");
        } else {
            asm volatile("cp.async.wait_group 0;");
        }
        __syncthreads();

        uint32_t stage = smb + s * CT_STAGE_BYTES;
#pragma unroll
        for (int kk = 0; kk < 2; kk++) {
            uint32_t ah[4][4], al[4][4];
#pragma unroll
            for (int mf = 0; mf < 4; mf++) {
                uint32_t addr = stage + ((kk * 16 + aMem_r) * CT_STRIDE
                              + aMem_c + mf * 16) * 2;
                ldsm_x4_t(ah[mf], addr);
                ldsm_x4_t(al[mf], addr + CT_ARR_BYTES);
            }
            uint32_t bh[4][2], bl[4][2];
#pragma unroll
            for (int ng = 0; ng < 2; ng++) {
                uint32_t addr = stage + 2 * CT_ARR_BYTES
                              + ((kk * 16 + bMem_r) * CT_STRIDE + bMem_c + ng * 16) * 2;
                uint32_t r[4];
                ldsm_x4_t(r, addr);
                bh[2*ng][0] = r[0]; bh[2*ng][1] = r[1];
                bh[2*ng+1][0] = r[2]; bh[2*ng+1][1] = r[3];
                ldsm_x4_t(r, addr + CT_ARR_BYTES);
                bl[2*ng][0] = r[0]; bl[2*ng][1] = r[1];
                bl[2*ng+1][0] = r[2]; bl[2*ng+1][1] = r[3];
            }
#pragma unroll
            for (int mf = 0; mf < 4; mf++)
#pragma unroll
                for (int nf = 0; nf < 4; nf++) {
                    mma_bf16(acc[mf][nf], ah[mf], bh[nf][0], bh[nf][1]);
                    mma_bf16(acc[mf][nf], ah[mf], bl[nf][0], bl[nf][1]);
                    mma_bf16(acc[mf][nf], al[mf], bh[nf][0], bh[nf][1]);
                }
        }
        __syncthreads();
    }

    int gr = lane >> 2, tig = lane & 3;
    float* Tp = g_T + (size_t)bg * HD * HD;
    const float* a7 = g_apow + ((size_t)7 * BB + b) * HD;
#pragma unroll
    for (int mf = 0; mf < 4; mf++) {
        int d0r = m0 + wm * 64 + mf * 16 + gr;
        float s0 = a7[d0r], s1 = a7[d0r + 8];
#pragma unroll
        for (int nf = 0; nf < 4; nf++) {
            int col = n0 + wn * 32 + nf * 8 + tig * 2;
            float* p0 = Tp + (size_t)d0r * HD + col;
            float* p1 = Tp + (size_t)(d0r + 8) * HD + col;
            *(float2*)p0 = make_float2(acc[mf][nf][0] * s0, acc[mf][nf][1] * s0);
            *(float2*)p1 = make_float2(acc[mf][nf][2] * s1, acc[mf][nf][3] * s1);
        }
    }
}

// ================= sequential scan (vectorized x4) =================
__global__ __launch_bounds__(256) void scan_kernel() {
    int b = blockIdx.y;
    int idx = blockIdx.x * 256 + threadIdx.x;   // over 768*768/4
    int d = idx / (HD / 4), h4 = (idx % (HD / 4)) * 4;
    float a8 = g_apow[((size_t)8 * BB + b) * HD + d];
    float4 carry = make_float4(0.f, 0.f, 0.f, 0.f);
    size_t base = ((size_t)b * 7) * HD * HD + (size_t)d * HD + h4;
#pragma unroll
    for (int g = 0; g < 7; g++) {
        float4 tv = *(const float4*)&g_T[base + (size_t)g * HD * HD];
        carry.x = fmaf(a8, carry.x, tv.x);
        carry.y = fmaf(a8, carry.y, tv.y);
        carry.z = fmaf(a8, carry.z, tv.z);
        carry.w = fmaf(a8, carry.w, tv.w);
        __nv_bfloat162 l0, l1;
        __nv_bfloat162 h0 = split_hi(carry.x, carry.y, l0);
        __nv_bfloat162 h1 = split_hi(carry.z, carry.w, l1);
        size_t o = base + (size_t)g * HD * HD;
        *(__nv_bfloat162*)&g_Sh[o]     = h0;
        *(__nv_bfloat162*)&g_Sh[o + 2] = h1;
        *(__nv_bfloat162*)&g_Sl[o]     = l0;
        *(__nv_bfloat162*)&g_Sl[o + 2] = l1;
    }
}

// ================= inter-chunk (k-chunk 48) =================
__global__ __launch_bounds__(256, 2) void inter_kernel(float* __restrict__ out) {
    extern __shared__ char sm[];
    uint32_t smb = smem_u32(sm);
    int t = threadIdx.x, lane = t & 31, w = t >> 5;
    int wm = w & 1, wn = w >> 1;
    int nb = blockIdx.x * 128;
    int mb = blockIdx.y * 128;
    int combo = blockIdx.z;
    int b = combo / 7, gm1 = combo % 7, g = gm1 + 1;
    size_t arow0 = (size_t)b * SSEQ + (size_t)g * 512 + mb;
    size_t srow0 = ((size_t)b * 7 + gm1) * HD * HD;

    float acc[4][4][4];
#pragma unroll
    for (int i = 0; i < 4; i++)
#pragma unroll
        for (int j = 0; j < 4; j++)
#pragma unroll
            for (int q = 0; q < 4; q++) acc[i][j][q] = 0.0f;

    auto issue = [&](int s, int k0) {
#pragma unroll
        for (int q = 0; q < 12; q++) {
            int id = t + q * 256;
            int arr = id / 768, rem = id % 768;
            int row = rem / 6, c = (rem % 6) * 8;
            const __nv_bfloat16* gp;
            if (arr == 0)      gp = g_Qh + (arow0 + row) * HD + k0 + c;
            else if (arr == 1) gp = g_Ql + (arow0 + row) * HD + k0 + c;
            else if (arr == 2) gp = g_Sh + srow0 + (size_t)(nb + row) * HD + k0 + c;
            else               gp = g_Sl + srow0 + (size_t)(nb + row) * HD + k0 + c;
            uint32_t sa = smb + s * QKV_STAGE_BYTES + arr * QKV_ARR_BYTES
                        + (row * QKV_STRIDE + c) * 2;
            cpasync16(sa, gp);
        }
        asm volatile("cp.async.commit_group;");
    };

    issue(0, 0);

    int aRow = wm * 64 + (lane & 15);
    int aColSel = (lane >> 4) * 8;
    int bRow = wn * 32 + (lane & 7) + ((lane >> 4) << 3);
    int bColSel = ((lane >> 3) & 1) * 8;

    for (int it = 0; it < 16; it++) {
        int s = it & 1;
        if (it + 1 < 16) {
            issue(1 - s, (it + 1) * QKV_KC);
            asm volatile("cp.async.wait_group 1;");
        } else {
            asm volatile("cp.async.wait_group 0;");
        }
        __syncthreads();

        uint32_t stage = smb + s * QKV_STAGE_BYTES;
#pragma unroll
        for (int kk = 0; kk < 3; kk++) {
            int aCol = kk * 16 + aColSel;
            int bCol = kk * 16 + bColSel;
            uint32_t ah[4][4], al[4][4];
#pragma unroll
            for (int mf = 0; mf < 4; mf++) {
                uint32_t addr = stage + ((aRow + mf * 16) * QKV_STRIDE + aCol) * 2;
                ldsm_x4(ah[mf], addr);
                ldsm_x4(al[mf], addr + QKV_ARR_BYTES);
            }
            uint32_t bh[4][2], bl[4][2];
#pragma unroll
            for (int ng = 0; ng < 2; ng++) {
                uint32_t addr = stage + 2 * QKV_ARR_BYTES
                              + ((bRow + ng * 16) * QKV_STRIDE + bCol) * 2;
                uint32_t r[4];
                ldsm_x4(r, addr);
                bh[2*ng][0] = r[0]; bh[2*ng][1] = r[1];
                bh[2*ng+1][0] = r[2]; bh[2*ng+1][1] = r[3];
                ldsm_x4(r, addr + QKV_ARR_BYTES);
                bl[2*ng][0] = r[0]; bl[2*ng][1] = r[1];
                bl[2*ng+1][0] = r[2]; bl[2*ng+1][1] = r[3];
            }
#pragma unroll
            for (int mf = 0; mf < 4; mf++)
#pragma unroll
                for (int nf = 0; nf < 4; nf++) {
                    mma_bf16(acc[mf][nf], ah[mf], bh[nf][0], bh[nf][1]);
                    mma_bf16(acc[mf][nf], ah[mf], bl[nf][0], bl[nf][1]);
                    mma_bf16(acc[mf][nf], al[mf], bh[nf][0], bh[nf][1]);
                }
        }
        __syncthreads();
    }

    int gr = lane >> 2, tig = lane & 3;
    int p = blockIdx.y * 2 + wm + 1;
    const float* sc = g_apow + ((size_t)p * BB + b) * HD;
#pragma unroll
    for (int mf = 0; mf < 4; mf++) {
        size_t row = arow0 + wm * 64 + mf * 16 + gr;
#pragma unroll
        for (int nf = 0; nf < 4; nf++) {
            int col = nb + wn * 32 + nf * 8 + tig * 2;
            float s0 = sc[col], s1 = sc[col + 1];
            float* p0 = out + row * HD + col;
            float* p1 = out + (row + 8) * HD + col;
            float2 v0 = *(float2*)p0, v1 = *(float2*)p1;
            v0.x += acc[mf][nf][0] * s0; v0.y += acc[mf][nf][1] * s1;
            v1.x += acc[mf][nf][2] * s0; v1.y += acc[mf][nf][3] * s1;
            *(float2*)p0 = v0; *(float2*)p1 = v1;
        }
    }
}

// ================= intra-chunk cross-block (double-buffered) =================
#define IN_PSTRIDE 456
#define IN_PBYTES  58368
#define IN_STG     116736
#define IN_S1ARR   9216
#define IN_S1STAGE 36864
#define IN_S2ARR   17408
#define IN_S2STAGE 34816
#define IN_SMEM    190464

__global__ __launch_bounds__(256) void intra_kernel(float* __restrict__ out) {
    extern __shared__ char sm[];
    uint32_t smb = smem_u32(sm);
    uint32_t Ph = smb, Pl = smb + IN_PBYTES, STG = smb + IN_STG;
    int t = threadIdx.x, lane = t & 31, w = t >> 5;
    int wm = w & 1, wn = w >> 1;
    int tt = blockIdx.x + 1;
    int g = blockIdx.y, b = blockIdx.z;
    size_t qrow0 = (size_t)b * SSEQ + (size_t)(g * 8 + tt) * 64;
    size_t krow0 = (size_t)b * SSEQ + (size_t)g * 512;
    int gr = lane >> 2, tig = lane & 3;

    auto issue1 = [&](int s, int j, int kc) {
#pragma unroll
        for (int q = 0; q < 8; q++) {
            int id = t + q * 256;
            int arr = id >> 9, rem = id & 511;
            int row = rem >> 3, cc = (rem & 7) * 8;
            const __nv_bfloat16* gp;
            if (arr == 0)      gp = g_Qh + (qrow0 + row) * HD + kc * 64 + cc;
            else if (arr == 1) gp = g_Ql + (qrow0 + row) * HD + kc * 64 + cc;
            else if (arr == 2) gp = g_Kh + (krow0 + j * 64 + row) * HD + kc * 64 + cc;
            else               gp = g_Kl + (krow0 + j * 64 + row) * HD + kc * 64 + cc;
            cpasync16(STG + s * IN_S1STAGE + arr * IN_S1ARR + (row * 72 + cc) * 2, gp);
        }
        asm volatile("cp.async.commit_group;");
    };

    float pacc[2][2][4];
    int total1 = tt * 12;
    issue1(0, 0, 0);
    for (int it = 0; it < total1; it++) {
        int s = it & 1;
        int kc = it % 12;
        if (kc == 0) {
#pragma unroll
            for (int i = 0; i < 2; i++)
#pragma unroll
                for (int q = 0; q < 2; q++)
#pragma unroll
                    for (int e = 0; e < 4; e++) pacc[i][q][e] = 0.0f;
        }
        if (it + 1 < total1) {
            issue1(1 - s, (it + 1) / 12, (it + 1) % 12);
            asm volatile("cp.async.wait_group 1;");
        } else {
            asm volatile("cp.async.wait_group 0;");
        }
        __syncthreads();

        uint32_t stg = STG + s * IN_S1STAGE;
#pragma unroll
        for (int kk = 0; kk < 4; kk++) {
            uint32_t ah[2][4], al[2][4];
#pragma unroll
            for (int mf = 0; mf < 2; mf++) {
                uint32_t addr = stg + ((wm * 32 + mf * 16 + (lane & 15)) * 72
                              + kk * 16 + (lane >> 4) * 8) * 2;
                ldsm_x4(ah[mf], addr);
                ldsm_x4(al[mf], addr + IN_S1ARR);
            }
            uint32_t bh[2][2], bl[2][2];
            {
                uint32_t addr = stg + 2 * IN_S1ARR
                              + ((wn * 16 + (lane & 7) + ((lane >> 4) << 3)) * 72
                              + kk * 16 + ((lane >> 3) & 1) * 8) * 2;
                uint32_t r[4];
                ldsm_x4(r, addr);
                bh[0][0] = r[0]; bh[0][1] = r[1]; bh[1][0] = r[2]; bh[1][1] = r[3];
                ldsm_x4(r, addr + IN_S1ARR);
                bl[0][0] = r[0]; bl[0][1] = r[1]; bl[1][0] = r[2]; bl[1][1] = r[3];
            }
#pragma unroll
            for (int mf = 0; mf < 2; mf++)
#pragma unroll
                for (int nf = 0; nf < 2; nf++) {
                    mma_bf16(pacc[mf][nf], ah[mf], bh[nf][0], bh[nf][1]);
                    mma_bf16(pacc[mf][nf], ah[mf], bl[nf][0], bl[nf][1]);
                    mma_bf16(pacc[mf][nf], al[mf], bh[nf][0], bh[nf][1]);
                }
        }

        if (kc == 11) {
            int j = it / 12;
#pragma unroll
            for (int mf = 0; mf < 2; mf++)
#pragma unroll
                for (int nf = 0; nf < 2; nf++) {
                    int row = wm * 32 + mf * 16 + gr;
                    int col = j * 64 + wn * 16 + nf * 8 + tig * 2;
#pragma unroll
                    for (int half = 0; half < 2; half++) {
                        __nv_bfloat162 lp;
                        __nv_bfloat162 hp = split_hi(pacc[mf][nf][half*2],
                                                     pacc[mf][nf][half*2+1], lp);
                        uint32_t off = ((row + half * 8) * IN_PSTRIDE + col) * 2;
                        *(__nv_bfloat162*)(sm + (Ph - smb) + off) = hp;
                        *(__nv_bfloat162*)(sm + (Pl - smb) + off) = lp;
                    }
                }
        }
        __syncthreads();
    }

    auto issue2 = [&](int s, int dt, int ec) {
#pragma unroll
        for (int q = 0; q < 8; q++) {
            int id = t + q * 256;
            int arr = id >> 10, rem = id & 1023;
            int row = rem >> 4, cc = (rem & 15) * 8;
            const __nv_bfloat16* gp = (arr == 0)
                ? g_Vsh + (krow0 + ec * 64 + row) * HD + dt * 128 + cc
                : g_Vsl + (krow0 + ec * 64 + row) * HD + dt * 128 + cc;
            cpasync16(STG + s * IN_S2STAGE + arr * IN_S2ARR + (row * 136 + cc) * 2, gp);
        }
        asm volatile("cp.async.commit_group;");
    };

    const float* sc = g_apow + ((size_t)tt * BB + b) * HD;
    float oacc[2][4][4];
    int total2 = 6 * tt;
    issue2(0, 0, 0);
    for (int it = 0; it < total2; it++) {
        int s = it & 1;
        int dt = it / tt, ec = it % tt;
        if (ec == 0) {
#pragma unroll
            for (int i = 0; i < 2; i++)
#pragma unroll
                for (int q = 0; q < 4; q++)
#pragma unroll
                    for (int e = 0; e < 4; e++) oacc[i][q][e] = 0.0f;
        }
        if (it + 1 < total2) {
            issue2(1 - s, (it + 1) / tt, (it + 1) % tt);
            asm volatile("cp.async.wait_group 1;");
        } else {
            asm volatile("cp.async.wait_group 0;");
        }
        __syncthreads();

        uint32_t stg = STG + s * IN_S2STAGE;
#pragma unroll
        for (int kk = 0; kk < 4; kk++) {
            uint32_t ah[2][4], al[2][4];
#pragma unroll
            for (int mf = 0; mf < 2; mf++) {
                uint32_t addr = Ph + ((wm * 32 + mf * 16 + (lane & 15)) * IN_PSTRIDE
                              + ec * 64 + kk * 16 + (lane >> 4) * 8) * 2;
                ldsm_x4(ah[mf], addr);
                ldsm_x4(al[mf], addr + IN_PBYTES);
            }
            uint32_t bh[4][2], bl[4][2];
#pragma unroll
            for (int ng = 0; ng < 2; ng++) {
                uint32_t addr = stg + ((kk * 16 + ((lane >> 3) & 1) * 8 + (lane & 7)) * 136
                              + wn * 32 + ng * 16 + (lane >> 4) * 8) * 2;
                uint32_t r[4];
                ldsm_x4_t(r, addr);
                bh[2*ng][0] = r[0]; bh[2*ng][1] = r[1];
                bh[2*ng+1][0] = r[2]; bh[2*ng+1][1] = r[3];
                ldsm_x4_t(r, addr + IN_S2ARR);
                bl[2*ng][0] = r[0]; bl[2*ng][1] = r[1];
                bl[2*ng+1][0] = r[2]; bl[2*ng+1][1] = r[3];
            }
#pragma unroll
            for (int mf = 0; mf < 2; mf++)
#pragma unroll
                for (int nf = 0; nf < 4; nf++) {
                    mma_bf16(oacc[mf][nf], ah[mf], bh[nf][0], bh[nf][1]);
                    mma_bf16(oacc[mf][nf], al[mf], bh[nf][0], bh[nf][1]);
                    mma_bf16(oacc[mf][nf], ah[mf], bl[nf][0], bl[nf][1]);
                }
        }

        if (ec == tt - 1) {
#pragma unroll
            for (int mf = 0; mf < 2; mf++) {
                size_t row = qrow0 + wm * 32 + mf * 16 + gr;
#pragma unroll
                for (int nf = 0; nf < 4; nf++) {
                    int col = dt * 128 + wn * 32 + nf * 8 + tig * 2;
                    float s0 = sc[col], s1 = sc[col + 1];
                    float* p0 = out + row * HD + col;
                    float* p1 = out + (row + 8) * HD + col;
                    float2 v0 = *(float2*)p0, v1 = *(float2*)p1;
                    v0.x += oacc[mf][nf][0] * s0; v0.y += oacc[mf][nf][1] * s1;
                    v1.x += oacc[mf][nf][2] * s0; v1.y += oacc[mf][nf][3] * s1;
                    *(float2*)p0 = v0; *(float2*)p1 = v1;
                }
            }
        }
        __syncthreads();
    }
}

// ================= launch =================
extern "C" void kernel_launch(void* const* d_in, const int* in_sizes, int n_in,
                              void* d_out, int out_size)
{
    const float* x  = (const float*)d_in[0];
    const float* Wq = (const float*)d_in[1];
    const float* Wk = (const float*)d_in[2];
    const float* Wv = (const float*)d_in[3];
    const float* W1 = (const float*)d_in[4];
    const float* W2 = (const float*)d_in[5];
    const float* bv = (const float*)d_in[6];
    float* out = (float*)d_out;

    cudaFuncSetAttribute((const void*)qkv_mma_kernel,
                         cudaFuncAttributeMaxDynamicSharedMemorySize, QKV_SMEM);
    cudaFuncSetAttribute((const void*)inter_kernel,
                         cudaFuncAttributeMaxDynamicSharedMemorySize, QKV_SMEM);
    cudaFuncSetAttribute((const void*)chunk_total_kernel,
                         cudaFuncAttributeMaxDynamicSharedMemorySize, 69632);
    cudaFuncSetAttribute((const void*)intra_kernel,
                         cudaFuncAttributeMaxDynamicSharedMemorySize, IN_SMEM);
    cudaFuncSetAttribute((const void*)attn_mma_kernel,
                         cudaFuncAttributeMaxDynamicSharedMemorySize, AT_SMEM);
    cudaFuncSetAttribute((const void*)t16_kernel,
                         cudaFuncAttributeMaxDynamicSharedMemorySize, 52224);
    cudaFuncSetAttribute((const void*)sig_kernel,
                         cudaFuncAttributeMaxDynamicSharedMemorySize, 53248);

    convert_x_kernel<<<6144, 256>>>(x);
    convert_w_kernel<<<dim3(64, 1, 3), 256>>>(Wq, Wk, Wv);
    t16_kernel<<<4096, 256, 52224>>>(x, W1);
    sig_kernel<<<dim3(64, BB), 256, 53248>>>(W2, bv);
    powers_kernel<<<24, 256>>>();

    qkv_mma_kernel<<<dim3(6, 256, 3), 256, QKV_SMEM>>>();

    attn_mma_kernel<<<dim3(NBLK, BB), 256, AT_SMEM>>>(out);

    chunk_total_kernel<<<dim3(36, 56), 256, 69632>>>();
    scan_kernel<<<dim3(576, BB), 256>>>();
    inter_kernel<<<dim3(6, 4, 56), 256, QKV_SMEM>>>(out);
    intra_kernel<<<dim3(7, 8, 8), 256, IN_SMEM>>>(out);
}

// round 17
// speedup vs baseline: 1.7087x; 1.1314x over previous
#include <cuda_runtime.h>
#include <cuda_bf16.h>
#include <cuda_fp16.h>
#include <math.h>
#include <stdint.h>

#define BB   8
#define SSEQ 4096
#define HD   768
#define CBLK 64
#define NBLK 64

// ---- device scratch ----
__device__ float g_a[BB*HD];
__device__ float g_t16[(size_t)BB*SSEQ*16];
__device__ __half g_xh[(size_t)BB*SSEQ*HD];           // fp16 hi of x
__device__ __half g_xl[(size_t)BB*SSEQ*HD];           // fp16 lo of x
__device__ __half g_Wh[3*HD*HD];                      // W^T (n-major) fp16
__device__ __nv_bfloat16 g_Qh[(size_t)BB*SSEQ*HD];
__device__ __nv_bfloat16 g_Ql[(size_t)BB*SSEQ*HD];
__device__ __nv_bfloat16 g_Kh[(size_t)BB*SSEQ*HD];
__device__ __nv_bfloat16 g_Kl[(size_t)BB*SSEQ*HD];
__device__ __nv_bfloat16 g_Vsh[(size_t)BB*SSEQ*HD];   // V * a^{-j_local}
__device__ __nv_bfloat16 g_Vsl[(size_t)BB*SSEQ*HD];
__device__ float g_T[(size_t)BB*7*HD*HD];
__device__ __nv_bfloat16 g_Sh[(size_t)BB*7*HD*HD];
__device__ __nv_bfloat16 g_Sl[(size_t)BB*7*HD*HD];
__device__ float g_apow[9*BB*HD];
__device__ float g_ainv[8*BB*HD];

__device__ __forceinline__ uint32_t smem_u32(const void* p) {
    uint32_t a;
    asm("{ .reg .u64 t; cvta.to.shared.u64 t, %1; cvt.u32.u64 %0, t; }"
        : "=r"(a) : "l"(p));
    return a;
}
__device__ __forceinline__ void ldsm_x4(uint32_t (&r)[4], uint32_t addr) {
    asm volatile("ldmatrix.sync.aligned.m8n8.x4.shared.b16 {%0,%1,%2,%3}, [%4];"
                 : "=r"(r[0]), "=r"(r[1]), "=r"(r[2]), "=r"(r[3]) : "r"(addr));
}
__device__ __forceinline__ void ldsm_x4_t(uint32_t (&r)[4], uint32_t addr) {
    asm volatile("ldmatrix.sync.aligned.m8n8.x4.trans.shared.b16 {%0,%1,%2,%3}, [%4];"
                 : "=r"(r[0]), "=r"(r[1]), "=r"(r[2]), "=r"(r[3]) : "r"(addr));
}
__device__ __forceinline__ void mma_bf16(float (&c)[4], const uint32_t a[4],
                                         const uint32_t b0, const uint32_t b1) {
    asm volatile(
        "mma.sync.aligned.m16n8k16.row.col.f32.bf16.bf16.f32 "
        "{%0,%1,%2,%3}, {%4,%5,%6,%7}, {%8,%9}, {%0,%1,%2,%3};"
        : "+f"(c[0]), "+f"(c[1]), "+f"(c[2]), "+f"(c[3])
        : "r"(a[0]), "r"(a[1]), "r"(a[2]), "r"(a[3]), "r"(b0), "r"(b1));
}
__device__ __forceinline__ void mma_fp16(float (&c)[4], const uint32_t a[4],
                                         const uint32_t b0, const uint32_t b1) {
    asm volatile(
        "mma.sync.aligned.m16n8k16.row.col.f32.f16.f16.f32 "
        "{%0,%1,%2,%3}, {%4,%5,%6,%7}, {%8,%9}, {%0,%1,%2,%3};"
        : "+f"(c[0]), "+f"(c[1]), "+f"(c[2]), "+f"(c[3])
        : "r"(a[0]), "r"(a[1]), "r"(a[2]), "r"(a[3]), "r"(b0), "r"(b1));
}
__device__ __forceinline__ void cpasync16(uint32_t sa, const void* gp) {
    asm volatile("cp.async.cg.shared.global [%0], [%1], 16;" :: "r"(sa), "l"(gp));
}
__device__ __forceinline__ __nv_bfloat162 split_hi(float v0, float v1,
                                                   __nv_bfloat162& lo) {
    __nv_bfloat16 h0 = __float2bfloat16(v0);
    __nv_bfloat16 h1 = __float2bfloat16(v1);
    lo.x = __float2bfloat16(v0 - __bfloat162float(h0));
    lo.y = __float2bfloat16(v1 - __bfloat162float(h1));
    __nv_bfloat162 hi; hi.x = h0; hi.y = h1;
    return hi;
}

// ================= conversions (zero_a folded in) =================
__global__ void convert_x_kernel(const float* __restrict__ x) {
    size_t gid0 = (size_t)blockIdx.x * blockDim.x + threadIdx.x;
    if (gid0 < BB * HD) g_a[gid0] = 0.0f;
    size_t n4 = (size_t)BB * SSEQ * HD / 4;
    for (size_t i = gid0; i < n4; i += (size_t)gridDim.x * blockDim.x) {
        float4 v = ((const float4*)x)[i];
        __half h0 = __float2half(v.x);
        __half h1 = __float2half(v.y);
        __half h2 = __float2half(v.z);
        __half h3 = __float2half(v.w);
        __half l0 = __float2half(v.x - __half2float(h0));
        __half l1 = __float2half(v.y - __half2float(h1));
        __half l2 = __float2half(v.z - __half2float(h2));
        __half l3 = __float2half(v.w - __half2float(h3));
        __half2 ph0; ph0.x = h0; ph0.y = h1;
        __half2 ph1; ph1.x = h2; ph1.y = h3;
        __half2 pl0; pl0.x = l0; pl0.y = l1;
        __half2 pl1; pl1.x = l2; pl1.y = l3;
        ((__half2*)g_xh)[2*i]   = ph0;
        ((__half2*)g_xh)[2*i+1] = ph1;
        ((__half2*)g_xl)[2*i]   = pl0;
        ((__half2*)g_xl)[2*i+1] = pl1;
    }
}

__global__ void convert_w_kernel(const float* __restrict__ Wq,
                                 const float* __restrict__ Wk,
                                 const float* __restrict__ Wv) {
    int w = blockIdx.z;
    const float* W = (w == 0) ? Wq : ((w == 1) ? Wk : Wv);
    __half* th = g_Wh + (size_t)w * HD * HD;
    for (int idx = blockIdx.x * 256 + threadIdx.x; idx < HD * HD; idx += gridDim.x * 256) {
        int k = idx / HD, n = idx % HD;
        th[(size_t)n * HD + k] = __float2half(W[idx]);
    }
}

// ================= gate pipeline =================
__global__ __launch_bounds__(256) void t16_kernel(const float* __restrict__ x,
                                                  const float* __restrict__ W1) {
    extern __shared__ char sm[];
    float* W1s = (float*)sm;   // [768][17]
    int t = threadIdx.x;
    for (int i = t; i < HD * 16; i += 256) {
        int r = i >> 4, c = i & 15;
        W1s[r * 17 + c] = W1[i];
    }
    __syncthreads();
    int w = t >> 5, lane = t & 31;
    int row = blockIdx.x * 8 + w;
    const float* xr = x + (size_t)row * HD;
    float tp[16];
#pragma unroll
    for (int j = 0; j < 16; j++) tp[j] = 0.0f;
    for (int i = lane; i < HD; i += 32) {
        float xv = xr[i];
        const float* w1r = &W1s[i * 17];
#pragma unroll
        for (int j = 0; j < 16; j++) tp[j] = fmaf(xv, w1r[j], tp[j]);
    }
#pragma unroll
    for (int off = 16; off > 0; off >>= 1)
#pragma unroll
        for (int j = 0; j < 16; j++)
            tp[j] += __shfl_xor_sync(0xffffffffu, tp[j], off);
    if (lane == 0) {
        float* op = g_t16 + (size_t)row * 16;
#pragma unroll
        for (int q = 0; q < 4; q++)
            ((float4*)op)[q] = make_float4(tp[q*4], tp[q*4+1], tp[q*4+2], tp[q*4+3]);
    }
}

__global__ __launch_bounds__(256) void sig_kernel(const float* __restrict__ W2,
                                                  const float* __restrict__ bvec) {
    extern __shared__ char sm[];
    float* W2s = (float*)sm;             // [16][768]
    float* tbuf = (float*)sm + 16 * HD;  // [64][16]
    int t = threadIdx.x;
    int b = blockIdx.y, sc0 = blockIdx.x * 64;
    for (int i = t; i < 16 * HD; i += 256) W2s[i] = W2[i];
    {
        const float* tp = g_t16 + ((size_t)b * SSEQ + sc0) * 16;
        for (int i = t; i < 64 * 16; i += 256) tbuf[i] = tp[i];
    }
    __syncthreads();

    int d0 = t, d1 = t + 256, d2 = t + 512;
    float bv0 = bvec[d0], bv1 = bvec[d1], bv2 = bvec[d2];
    float acc0 = 0.0f, acc1 = 0.0f, acc2 = 0.0f;
    for (int r = 0; r < 64; r++) {
        const float* tr = &tbuf[r * 16];
        float h0 = bv0, h1 = bv1, h2 = bv2;
#pragma unroll
        for (int j = 0; j < 16; j++) {
            float tv = tr[j];
            h0 = fmaf(tv, W2s[j * HD + d0], h0);
            h1 = fmaf(tv, W2s[j * HD + d1], h1);
            h2 = fmaf(tv, W2s[j * HD + d2], h2);
        }
        acc0 += __expf(-0.0625f * __logf(1.0f + __expf(-h0)));
        acc1 += __expf(-0.0625f * __logf(1.0f + __expf(-h1)));
        acc2 += __expf(-0.0625f * __logf(1.0f + __expf(-h2)));
    }
    const float inv = 1.0f / (float)SSEQ;
    atomicAdd(&g_a[b * HD + d0], acc0 * inv);
    atomicAdd(&g_a[b * HD + d1], acc1 * inv);
    atomicAdd(&g_a[b * HD + d2], acc2 * inv);
}

__global__ void powers_kernel() {
    int idx = blockIdx.x * blockDim.x + threadIdx.x;
    if (idx >= BB * HD) return;
    int b = idx / HD, d = idx % HD;
    float a = g_a[idx];
    float p = 1.0f;
#pragma unroll
    for (int q = 0; q <= 8; q++) { g_apow[((size_t)q * BB + b) * HD + d] = p; p *= a; }
    float ia = 1.0f / a, pv = 1.0f;
#pragma unroll
    for (int q = 0; q < 8; q++) { g_ainv[((size_t)q * BB + b) * HD + d] = pv; pv *= ia; }
}

// ========== QKV mma: 2-term fp16 (A split, B single), k-chunk 48 ==========
#define QKV_KC 48
#define QKV_STRIDE 56            // 48 elems + 8 pad -> 112 B rows (16B multiple)
#define QKV_ARR_BYTES 14336      // 128 * 56 * 2
#define QKV_STAGE_BYTES 43008    // 3 arrays (xh, xl, Wh)
#define QKV_SMEM 86016

__global__ __launch_bounds__(256, 2) void qkv_mma_kernel() {
    extern __shared__ char sm[];
    uint32_t smb = smem_u32(sm);
    int t = threadIdx.x, lane = t & 31, w = t >> 5;
    int wm = w & 1, wn = w >> 1;
    int nb = blockIdx.x * 128;
    int mb = blockIdx.y * 128;
    int mat = blockIdx.z;
    const __half* Wh_g = g_Wh + (size_t)mat * HD * HD;

    float acc[4][4][4];
#pragma unroll
    for (int i = 0; i < 4; i++)
#pragma unroll
        for (int j = 0; j < 4; j++)
#pragma unroll
            for (int q = 0; q < 4; q++) acc[i][j][q] = 0.0f;

    // 2304 16B chunks per stage (128 rows x 6 chunks x 3 arrays), 9/thread
    auto issue = [&](int s, int k0) {
#pragma unroll
        for (int q = 0; q < 9; q++) {
            int id = t + q * 256;
            int arr = id / 768, rem = id % 768;
            int row = rem / 6, c = (rem % 6) * 8;
            const __half* gp;
            if (arr == 0)      gp = g_xh + (size_t)(mb + row) * HD + k0 + c;
            else if (arr == 1) gp = g_xl + (size_t)(mb + row) * HD + k0 + c;
            else               gp = Wh_g + (size_t)(nb + row) * HD + k0 + c;
            uint32_t sa = smb + s * QKV_STAGE_BYTES + arr * QKV_ARR_BYTES
                        + (row * QKV_STRIDE + c) * 2;
            cpasync16(sa, gp);
        }
        asm volatile("cp.async.commit_group;");
    };

    issue(0, 0);

    int aRow = wm * 64 + (lane & 15);
    int aColSel = (lane >> 4) * 8;
    int bRow = wn * 32 + (lane & 7) + ((lane >> 4) << 3);
    int bColSel = ((lane >> 3) & 1) * 8;

    for (int it = 0; it < 16; it++) {
        int s = it & 1;
        if (it + 1 < 16) {
            issue(1 - s, (it + 1) * QKV_KC);
            asm volatile("cp.async.wait_group 1;");
        } else {
            asm volatile("cp.async.wait_group 0;");
        }
        __syncthreads();

        uint32_t stage = smb + s * QKV_STAGE_BYTES;
#pragma unroll
        for (int kk = 0; kk < 3; kk++) {
            int aCol = kk * 16 + aColSel;
            int bCol = kk * 16 + bColSel;
            uint32_t ah[4][4], al[4][4];
#pragma unroll
            for (int mf = 0; mf < 4; mf++) {
                uint32_t addr = stage + ((aRow + mf * 16) * QKV_STRIDE + aCol) * 2;
                ldsm_x4(ah[mf], addr);
                ldsm_x4(al[mf], addr + QKV_ARR_BYTES);
            }
            uint32_t bh[4][2];
#pragma unroll
            for (int ng = 0; ng < 2; ng++) {
                uint32_t addr = stage + 2 * QKV_ARR_BYTES
                              + ((bRow + ng * 16) * QKV_STRIDE + bCol) * 2;
                uint32_t r[4];
                ldsm_x4(r, addr);
                bh[2*ng][0] = r[0]; bh[2*ng][1] = r[1];
                bh[2*ng+1][0] = r[2]; bh[2*ng+1][1] = r[3];
            }
#pragma unroll
            for (int mf = 0; mf < 4; mf++)
#pragma unroll
                for (int nf = 0; nf < 4; nf++) {
                    mma_fp16(acc[mf][nf], ah[mf], bh[nf][0], bh[nf][1]);
                    mma_fp16(acc[mf][nf], al[mf], bh[nf][0], bh[nf][1]);
                }
        }
        __syncthreads();
    }

    // fused epilogue: split hi/lo (V also scaled by a^{-j}); uniform branch on mat
    int g = lane >> 2, tig = lane & 3;
    if (mat < 2) {
        __nv_bfloat16* Oh = (mat == 0) ? g_Qh : g_Kh;
        __nv_bfloat16* Ol = (mat == 0) ? g_Ql : g_Kl;
#pragma unroll
        for (int mf = 0; mf < 4; mf++)
#pragma unroll
            for (int half = 0; half < 2; half++) {
                size_t grow = (size_t)(mb + wm * 64 + mf * 16 + g + half * 8);
#pragma unroll
                for (int nf = 0; nf < 4; nf++) {
                    int col = nb + wn * 32 + nf * 8 + tig * 2;
                    __nv_bfloat162 lo;
                    __nv_bfloat162 hi = split_hi(acc[mf][nf][half*2],
                                                 acc[mf][nf][half*2+1], lo);
                    *(__nv_bfloat162*)&Oh[grow * HD + col] = hi;
                    *(__nv_bfloat162*)&Ol[grow * HD + col] = lo;
                }
            }
    } else {
#pragma unroll
        for (int mf = 0; mf < 4; mf++)
#pragma unroll
            for (int half = 0; half < 2; half++) {
                int grow = mb + wm * 64 + mf * 16 + g + half * 8;
                int b = grow >> 12;
                int j = ((grow & 4095) >> 6) & 7;
                const float* ai = g_ainv + ((size_t)j * BB + b) * HD + nb + wn * 32;
#pragma unroll
                for (int nf = 0; nf < 4; nf++) {
                    int co = nf * 8 + tig * 2;
                    float2 av = *(const float2*)(ai + co);
                    float v0 = acc[mf][nf][half*2]     * av.x;
                    float v1 = acc[mf][nf][half*2 + 1] * av.y;
                    __nv_bfloat162 lo;
                    __nv_bfloat162 hi = split_hi(v0, v1, lo);
                    size_t off = (size_t)grow * HD + nb + wn * 32 + co;
                    *(__nv_bfloat162*)&g_Vsh[off] = hi;
                    *(__nv_bfloat162*)&g_Vsl[off] = lo;
                }
            }
    }
}

// ================= diag-block attention on tensor cores =================
#define AT_QSTRIDE 72
#define AT_ARR     9216
#define AT_STAGE   36864
#define AT_PF_OFF  73728
#define AT_M2_OFF  90624
#define AT_VARR    17408
#define AT_SMEM    109056

__global__ __launch_bounds__(256) void attn_mma_kernel(float* __restrict__ out) {
    extern __shared__ char sm[];
    uint32_t smb = smem_u32(sm);
    int t = threadIdx.x, lane = t & 31, w = t >> 5;
    int wm = w & 1, wn = w >> 1;
    int nb = blockIdx.x, b = blockIdx.y;
    int jloc = nb & 7;
    size_t row0 = (size_t)b * SSEQ + (size_t)nb * 64;
    int gr = lane >> 2, tig = lane & 3;

    float pacc[2][2][4];
#pragma unroll
    for (int i = 0; i < 2; i++)
#pragma unroll
        for (int q = 0; q < 2; q++)
#pragma unroll
            for (int e = 0; e < 4; e++) pacc[i][q][e] = 0.0f;

    auto issue1 = [&](int s, int kc) {
#pragma unroll
        for (int q = 0; q < 8; q++) {
            int id = t + q * 256;
            int arr = id >> 9, rem = id & 511;
            int row = rem >> 3, cc = (rem & 7) * 8;
            const __nv_bfloat16* gp;
            if (arr == 0)      gp = g_Qh + (row0 + row) * HD + kc * 64 + cc;
            else if (arr == 1) gp = g_Ql + (row0 + row) * HD + kc * 64 + cc;
            else if (arr == 2) gp = g_Kh + (row0 + row) * HD + kc * 64 + cc;
            else               gp = g_Kl + (row0 + row) * HD + kc * 64 + cc;
            cpasync16(smb + s * AT_STAGE + arr * AT_ARR + (row * AT_QSTRIDE + cc) * 2, gp);
        }
        asm volatile("cp.async.commit_group;");
    };

    issue1(0, 0);
    for (int kc = 0; kc < 12; kc++) {
        int s = kc & 1;
        if (kc + 1 < 12) {
            issue1(1 - s, kc + 1);
            asm volatile("cp.async.wait_group 1;");
        } else {
            asm volatile("cp.async.wait_group 0;");
        }
        __syncthreads();
        uint32_t stg = smb + s * AT_STAGE;
#pragma unroll
        for (int kk = 0; kk < 4; kk++) {
            uint32_t ah[2][4], al[2][4];
#pragma unroll
            for (int mf = 0; mf < 2; mf++) {
                uint32_t addr = stg + ((wm * 32 + mf * 16 + (lane & 15)) * AT_QSTRIDE
                              + kk * 16 + (lane >> 4) * 8) * 2;
                ldsm_x4(ah[mf], addr);
                ldsm_x4(al[mf], addr + AT_ARR);
            }
            uint32_t bh[2][2], bl[2][2];
            {
                uint32_t addr = stg + 2 * AT_ARR
                              + ((wn * 16 + (lane & 7) + ((lane >> 4) << 3)) * AT_QSTRIDE
                              + kk * 16 + ((lane >> 3) & 1) * 8) * 2;
                uint32_t r[4];
                ldsm_x4(r, addr);
                bh[0][0] = r[0]; bh[0][1] = r[1]; bh[1][0] = r[2]; bh[1][1] = r[3];
                ldsm_x4(r, addr + AT_ARR);
                bl[0][0] = r[0]; bl[0][1] = r[1]; bl[1][0] = r[2]; bl[1][1] = r[3];
            }
#pragma unroll
            for (int mf = 0; mf < 2; mf++)
#pragma unroll
                for (int nf = 0; nf < 2; nf++) {
                    mma_bf16(pacc[mf][nf], ah[mf], bh[nf][0], bh[nf][1]);
                    mma_bf16(pacc[mf][nf], ah[mf], bl[nf][0], bl[nf][1]);
                    mma_bf16(pacc[mf][nf], al[mf], bh[nf][0], bh[nf][1]);
                }
        }
        __syncthreads();
    }

    float* PfP = (float*)(sm + AT_PF_OFF);
#pragma unroll
    for (int mf = 0; mf < 2; mf++)
#pragma unroll
        for (int nf = 0; nf < 2; nf++) {
            int row = wm * 32 + mf * 16 + gr;
            int col = wn * 16 + nf * 8 + tig * 2;
            PfP[row * 66 + col]       = pacc[mf][nf][0];
            PfP[row * 66 + col + 1]   = pacc[mf][nf][1];
            PfP[(row + 8) * 66 + col]     = pacc[mf][nf][2];
            PfP[(row + 8) * 66 + col + 1] = pacc[mf][nf][3];
        }
    __syncthreads();

    {
        __nv_bfloat16* M2h = (__nv_bfloat16*)(sm + AT_M2_OFF);
        __nv_bfloat16* M2l = (__nv_bfloat16*)(sm + AT_M2_OFF + AT_ARR);
        const float scale = 1.0f / 27.712813f;
#pragma unroll
        for (int r8 = 0; r8 < 8; r8++) {
            int r = w * 8 + r8;
            float p0 = PfP[r * 66 + lane], p1 = PfP[r * 66 + lane + 32];
            float s0 = (lane <= r)        ? p0 * scale : 0.0f;
            float s1 = ((lane + 32) <= r) ? p1 * scale : 0.0f;
            float m = fmaxf(s0, s1);
#pragma unroll
            for (int off = 16; off; off >>= 1)
                m = fmaxf(m, __shfl_xor_sync(0xffffffffu, m, off));
            float e0 = expf(s0 - m), e1 = expf(s1 - m);
            float ssum = e0 + e1;
#pragma unroll
            for (int off = 16; off; off >>= 1)
                ssum += __shfl_xor_sync(0xffffffffu, ssum, off);
            float invz = 1.0f / ssum;
            float v0 = p0 + e0 * invz;
            float v1 = p1 + e1 * invz;
            __nv_bfloat16 h0 = __float2bfloat16(v0);
            __nv_bfloat16 h1 = __float2bfloat16(v1);
            M2h[r * AT_QSTRIDE + lane]      = h0;
            M2h[r * AT_QSTRIDE + lane + 32] = h1;
            M2l[r * AT_QSTRIDE + lane]      = __float2bfloat16(v0 - __bfloat162float(h0));
            M2l[r * AT_QSTRIDE + lane + 32] = __float2bfloat16(v1 - __bfloat162float(h1));
        }
    }
    __syncthreads();

    auto issue2 = [&](int s, int dt) {
#pragma unroll
        for (int q = 0; q < 8; q++) {
            int id = t + q * 256;
            int arr = id >> 10, rem = id & 1023;
            int row = rem >> 4, cc = (rem & 15) * 8;
            const __nv_bfloat16* gp = (arr == 0)
                ? g_Vsh + (row0 + row) * HD + dt * 128 + cc
                : g_Vsl + (row0 + row) * HD + dt * 128 + cc;
            cpasync16(smb + s * (2 * AT_VARR) + arr * AT_VARR + (row * 136 + cc) * 2, gp);
        }
        asm volatile("cp.async.commit_group;");
    };

    issue2(0, 0);
    const float* aj = g_apow + ((size_t)jloc * BB + b) * HD;
    for (int dt = 0; dt < 6; dt++) {
        int s = dt & 1;
        if (dt + 1 < 6) {
            issue2(1 - s, dt + 1);
            asm volatile("cp.async.wait_group 1;");
        } else {
            asm volatile("cp.async.wait_group 0;");
        }
        __syncthreads();

        float oacc[2][4][4];
#pragma unroll
        for (int i = 0; i < 2; i++)
#pragma unroll
            for (int q = 0; q < 4; q++)
#pragma unroll
                for (int e = 0; e < 4; e++) oacc[i][q][e] = 0.0f;

#pragma unroll
        for (int kk = 0; kk < 4; kk++) {
            uint32_t ah[2][4], al[2][4];
#pragma unroll
            for (int mf = 0; mf < 2; mf++) {
                uint32_t addr = smb + AT_M2_OFF
                              + ((wm * 32 + mf * 16 + (lane & 15)) * AT_QSTRIDE
                              + kk * 16 + (lane >> 4) * 8) * 2;
                ldsm_x4(ah[mf], addr);
                ldsm_x4(al[mf], addr + AT_ARR);
            }
            uint32_t bh[4][2], bl[4][2];
#pragma unroll
            for (int ng = 0; ng < 2; ng++) {
                uint32_t addr = smb + s * (2 * AT_VARR)
                              + ((kk * 16 + ((lane >> 3) & 1) * 8 + (lane & 7)) * 136
                              + wn * 32 + ng * 16 + (lane >> 4) * 8) * 2;
                uint32_t r[4];
                ldsm_x4_t(r, addr);
                bh[2*ng][0] = r[0]; bh[2*ng][1] = r[1];
                bh[2*ng+1][0] = r[2]; bh[2*ng+1][1] = r[3];
                ldsm_x4_t(r, addr + AT_VARR);
                bl[2*ng][0] = r[0]; bl[2*ng][1] = r[1];
                bl[2*ng+1][0] = r[2]; bl[2*ng+1][1] = r[3];
            }
#pragma unroll
            for (int mf = 0; mf < 2; mf++)
#pragma unroll
                for (int nf = 0; nf < 4; nf++) {
                    mma_bf16(oacc[mf][nf], ah[mf], bh[nf][0], bh[nf][1]);
                    mma_bf16(oacc[mf][nf], ah[mf], bl[nf][0], bl[nf][1]);
                    mma_bf16(oacc[mf][nf], al[mf], bh[nf][0], bh[nf][1]);
                }
        }
#pragma unroll
        for (int mf = 0; mf < 2; mf++) {
            size_t row = row0 + wm * 32 + mf * 16 + gr;
#pragma unroll
            for (int nf = 0; nf < 4; nf++) {
                int col = dt * 128 + wn * 32 + nf * 8 + tig * 2;
                float s0 = aj[col], s1 = aj[col + 1];
                *(float2*)&out[row * HD + col] =
                    make_float2(oacc[mf][nf][0] * s0, oacc[mf][nf][1] * s1);
                *(float2*)&out[(row + 8) * HD + col] =
                    make_float2(oacc[mf][nf][2] * s0, oacc[mf][nf][3] * s1);
            }
        }
        __syncthreads();
    }
}

// ================= chunk totals =================
#define CT_STRIDE 136
#define CT_ARR_BYTES 8704
#define CT_STAGE_BYTES 34816

__global__ __launch_bounds__(256) void chunk_total_kernel() {
    extern __shared__ char sm[];
    uint32_t smb = smem_u32(sm);
    int t = threadIdx.x, lane = t & 31, w = t >> 5;
    int wm = w & 1, wn = w >> 1;
    int tile = blockIdx.x;
    int m0 = (tile % 6) * 128;
    int n0 = (tile / 6) * 128;
    int bg = blockIdx.y;
    int b = bg / 7, g = bg % 7;
    size_t crow0 = (size_t)b * SSEQ + (size_t)g * 512;

    float acc[4][4][4];
#pragma unroll
    for (int i = 0; i < 4; i++)
#pragma unroll
        for (int j = 0; j < 4; j++)
#pragma unroll
            for (int q = 0; q < 4; q++) acc[i][j][q] = 0.0f;

    auto issue = [&](int s, int k0) {
#pragma unroll
        for (int q = 0; q < 8; q++) {
            int id = t + q * 256;
            int arr = id >> 9, rem = id & 511;
            int row = rem >> 4, c = (rem & 15) * 8;
            const __nv_bfloat16* gp;
            size_t go = (crow0 + k0 + row) * HD;
            if (arr == 0)      gp = g_Vsh + go + m0 + c;
            else if (arr == 1) gp = g_Vsl + go + m0 + c;
            else if (arr == 2) gp = g_Kh  + go + n0 + c;
            else               gp = g_Kl  + go + n0 + c;
            uint32_t sa = smb + s * CT_STAGE_BYTES + arr * CT_ARR_BYTES
                        + (row * CT_STRIDE + c) * 2;
            cpasync16(sa, gp);
        }
        asm volatile("cp.async.commit_group;");
    };

    issue(0, 0);

    int aMem_r = ((lane >> 4) << 3) + (lane & 7);
    int aMem_c = wm * 64 + ((lane >> 3) & 1) * 8;
    int bMem_r = ((lane >> 3) & 1) * 8 + (lane & 7);
    int bMem_c = wn * 32 + (lane >> 4) * 8;

    for (int it = 0; it < 16; it++) {
        int s = it & 1;
        if (it + 1 < 16) {
            issue(1 - s, (it + 1) * 32);
            asm volatile("cp.async.wait_group 1;");
        } else {
            asm volatile("cp.async.wait_group 0;");
        }
        __syncthreads();

        uint32_t stage = smb + s * CT_STAGE_BYTES;
#pragma unroll
        for (int kk = 0; kk < 2; kk++) {
            uint32_t ah[4][4], al[4][4];
#pragma unroll
            for (int mf = 0; mf < 4; mf++) {
                uint32_t addr = stage + ((kk * 16 + aMem_r) * CT_STRIDE
                              + aMem_c + mf * 16) * 2;
                ldsm_x4_t(ah[mf], addr);
                ldsm_x4_t(al[mf], addr + CT_ARR_BYTES);
            }
            uint32_t bh[4][2], bl[4][2];
#pragma unroll
            for (int ng = 0; ng < 2; ng++) {
                uint32_t addr = stage + 2 * CT_ARR_BYTES
                              + ((kk * 16 + bMem_r) * CT_STRIDE + bMem_c + ng * 16) * 2;
                uint32_t r[4];
                ldsm_x4_t(r, addr);
                bh[2*ng][0] = r[0]; bh[2*ng][1] = r[1];
                bh[2*ng+1][0] = r[2]; bh[2*ng+1][1] = r[3];
                ldsm_x4_t(r, addr + CT_ARR_BYTES);
                bl[2*ng][0] = r[0]; bl[2*ng][1] = r[1];
                bl[2*ng+1][0] = r[2]; bl[2*ng+1][1] = r[3];
            }
#pragma unroll
            for (int mf = 0; mf < 4; mf++)
#pragma unroll
                for (int nf = 0; nf < 4; nf++) {
                    mma_bf16(acc[mf][nf], ah[mf], bh[nf][0], bh[nf][1]);
                    mma_bf16(acc[mf][nf], ah[mf], bl[nf][0], bl[nf][1]);
                    mma_bf16(acc[mf][nf], al[mf], bh[nf][0], bh[nf][1]);
                }
        }
        __syncthreads();
    }

    int gr = lane >> 2, tig = lane & 3;
    float* Tp = g_T + (size_t)bg * HD * HD;
    const float* a7 = g_apow + ((size_t)7 * BB + b) * HD;
#pragma unroll
    for (int mf = 0; mf < 4; mf++) {
        int d0r = m0 + wm * 64 + mf * 16 + gr;
        float s0 = a7[d0r], s1 = a7[d0r + 8];
#pragma unroll
        for (int nf = 0; nf < 4; nf++) {
            int col = n0 + wn * 32 + nf * 8 + tig * 2;
            float* p0 = Tp + (size_t)d0r * HD + col;
            float* p1 = Tp + (size_t)(d0r + 8) * HD + col;
            *(float2*)p0 = make_float2(acc[mf][nf][0] * s0, acc[mf][nf][1] * s0);
            *(float2*)p1 = make_float2(acc[mf][nf][2] * s1, acc[mf][nf][3] * s1);
        }
    }
}

// ================= sequential scan (vectorized x4) =================
__global__ __launch_bounds__(256) void scan_kernel() {
    int b = blockIdx.y;
    int idx = blockIdx.x * 256 + threadIdx.x;   // over 768*768/4
    int d = idx / (HD / 4), h4 = (idx % (HD / 4)) * 4;
    float a8 = g_apow[((size_t)8 * BB + b) * HD + d];
    float4 carry = make_float4(0.f, 0.f, 0.f, 0.f);
    size_t base = ((size_t)b * 7) * HD * HD + (size_t)d * HD + h4;
#pragma unroll
    for (int g = 0; g < 7; g++) {
        float4 tv = *(const float4*)&g_T[base + (size_t)g * HD * HD];
        carry.x = fmaf(a8, carry.x, tv.x);
        carry.y = fmaf(a8, carry.y, tv.y);
        carry.z = fmaf(a8, carry.z, tv.z);
        carry.w = fmaf(a8, carry.w, tv.w);
        __nv_bfloat162 l0, l1;
        __nv_bfloat162 h0 = split_hi(carry.x, carry.y, l0);
        __nv_bfloat162 h1 = split_hi(carry.z, carry.w, l1);
        size_t o = base + (size_t)g * HD * HD;
        *(__nv_bfloat162*)&g_Sh[o]     = h0;
        *(__nv_bfloat162*)&g_Sh[o + 2] = h1;
        *(__nv_bfloat162*)&g_Sl[o]     = l0;
        *(__nv_bfloat162*)&g_Sl[o + 2] = l1;
    }
}

// ================= inter-chunk (k-chunk 48) =================
#define IT_STRIDE 56
#define IT_ARR_BYTES 14336
#define IT_STAGE_BYTES 57344
#define IT_SMEM 114688

__global__ __launch_bounds__(256, 2) void inter_kernel(float* __restrict__ out) {
    extern __shared__ char sm[];
    uint32_t smb = smem_u32(sm);
    int t = threadIdx.x, lane = t & 31, w = t >> 5;
    int wm = w & 1, wn = w >> 1;
    int nb = blockIdx.x * 128;
    int mb = blockIdx.y * 128;
    int combo = blockIdx.z;
    int b = combo / 7, gm1 = combo % 7, g = gm1 + 1;
    size_t arow0 = (size_t)b * SSEQ + (size_t)g * 512 + mb;
    size_t srow0 = ((size_t)b * 7 + gm1) * HD * HD;

    float acc[4][4][4];
#pragma unroll
    for (int i = 0; i < 4; i++)
#pragma unroll
        for (int j = 0; j < 4; j++)
#pragma unroll
            for (int q = 0; q < 4; q++) acc[i][j][q] = 0.0f;

    auto issue = [&](int s, int k0) {
#pragma unroll
        for (int q = 0; q < 12; q++) {
            int id = t + q * 256;
            int arr = id / 768, rem = id % 768;
            int row = rem / 6, c = (rem % 6) * 8;
            const __nv_bfloat16* gp;
            if (arr == 0)      gp = g_Qh + (arow0 + row) * HD + k0 + c;
            else if (arr == 1) gp = g_Ql + (arow0 + row) * HD + k0 + c;
            else if (arr == 2) gp = g_Sh + srow0 + (size_t)(nb + row) * HD + k0 + c;
            else               gp = g_Sl + srow0 + (size_t)(nb + row) * HD + k0 + c;
            uint32_t sa = smb + s * IT_STAGE_BYTES + arr * IT_ARR_BYTES
                        + (row * IT_STRIDE + c) * 2;
            cpasync16(sa, gp);
        }
        asm volatile("cp.async.commit_group;");
    };

    issue(0, 0);

    int aRow = wm * 64 + (lane & 15);
    int aColSel = (lane >> 4) * 8;
    int bRow = wn * 32 + (lane & 7) + ((lane >> 4) << 3);
    int bColSel = ((lane >> 3) & 1) * 8;

    for (int it = 0; it < 16; it++) {
        int s = it & 1;
        if (it + 1 < 16) {
            issue(1 - s, (it + 1) * QKV_KC);
            asm volatile("cp.async.wait_group 1;");
        } else {
            asm volatile("cp.async.wait_group 0;");
        }
        __syncthreads();

        uint32_t stage = smb + s * IT_STAGE_BYTES;
#pragma unroll
        for (int kk = 0; kk < 3; kk++) {
            int aCol = kk * 16 + aColSel;
            int bCol = kk * 16 + bColSel;
            uint32_t ah[4][4], al[4][4];
#pragma unroll
            for (int mf = 0; mf < 4; mf++) {
                uint32_t addr = stage + ((aRow + mf * 16) * IT_STRIDE + aCol) * 2;
                ldsm_x4(ah[mf], addr);
                ldsm_x4(al[mf], addr + IT_ARR_BYTES);
            }
            uint32_t bh[4][2], bl[4][2];
#pragma unroll
            for (int ng = 0; ng < 2; ng++) {
                uint32_t addr = stage + 2 * IT_ARR_BYTES
                              + ((bRow + ng * 16) * IT_STRIDE + bCol) * 2;
                uint32_t r[4];
                ldsm_x4(r, addr);
                bh[2*ng][0] = r[0]; bh[2*ng][1] = r[1];
                bh[2*ng+1][0] = r[2]; bh[2*ng+1][1] = r[3];
                ldsm_x4(r, addr + IT_ARR_BYTES);
                bl[2*ng][0] = r[0]; bl[2*ng][1] = r[1];
                bl[2*ng+1][0] = r[2]; bl[2*ng+1][1] = r[3];
            }
#pragma unroll
            for (int mf = 0; mf < 4; mf++)
#pragma unroll
                for (int nf = 0; nf < 4; nf++) {
                    mma_bf16(acc[mf][nf], ah[mf], bh[nf][0], bh[nf][1]);
                    mma_bf16(acc[mf][nf], ah[mf], bl[nf][0], bl[nf][1]);
                    mma_bf16(acc[mf][nf], al[mf], bh[nf][0], bh[nf][1]);
                }
        }
        __syncthreads();
    }

    int gr = lane >> 2, tig = lane & 3;
    int p = blockIdx.y * 2 + wm + 1;
    const float* sc = g_apow + ((size_t)p * BB + b) * HD;
#pragma unroll
    for (int mf = 0; mf < 4; mf++) {
        size_t row = arow0 + wm * 64 + mf * 16 + gr;
#pragma unroll
        for (int nf = 0; nf < 4; nf++) {
            int col = nb + wn * 32 + nf * 8 + tig * 2;
            float s0 = sc[col], s1 = sc[col + 1];
            float* p0 = out + row * HD + col;
            float* p1 = out + (row + 8) * HD + col;
            float2 v0 = *(float2*)p0, v1 = *(float2*)p1;
            v0.x += acc[mf][nf][0] * s0; v0.y += acc[mf][nf][1] * s1;
            v1.x += acc[mf][nf][2] * s0; v1.y += acc[mf][nf][3] * s1;
            *(float2*)p0 = v0; *(float2*)p1 = v1;
        }
    }
}

// ================= intra-chunk cross-block (double-buffered) =================
#define IN_PSTRIDE 456
#define IN_PBYTES  58368
#define IN_STG     116736
#define IN_S1ARR   9216
#define IN_S1STAGE 36864
#define IN_S2ARR   17408
#define IN_S2STAGE 34816
#define IN_SMEM    190464

__global__ __launch_bounds__(256) void intra_kernel(float* __restrict__ out) {
    extern __shared__ char sm[];
    uint32_t smb = smem_u32(sm);
    uint32_t Ph = smb, Pl = smb + IN_PBYTES, STG = smb + IN_STG;
    int t = threadIdx.x, lane = t & 31, w = t >> 5;
    int wm = w & 1, wn = w >> 1;
    int tt = blockIdx.x + 1;
    int g = blockIdx.y, b = blockIdx.z;
    size_t qrow0 = (size_t)b * SSEQ + (size_t)(g * 8 + tt) * 64;
    size_t krow0 = (size_t)b * SSEQ + (size_t)g * 512;
    int gr = lane >> 2, tig = lane & 3;

    auto issue1 = [&](int s, int j, int kc) {
#pragma unroll
        for (int q = 0; q < 8; q++) {
            int id = t + q * 256;
            int arr = id >> 9, rem = id & 511;
            int row = rem >> 3, cc = (rem & 7) * 8;
            const __nv_bfloat16* gp;
            if (arr == 0)      gp = g_Qh + (qrow0 + row) * HD + kc * 64 + cc;
            else if (arr == 1) gp = g_Ql + (qrow0 + row) * HD + kc * 64 + cc;
            else if (arr == 2) gp = g_Kh + (krow0 + j * 64 + row) * HD + kc * 64 + cc;
            else               gp = g_Kl + (krow0 + j * 64 + row) * HD + kc * 64 + cc;
            cpasync16(STG + s * IN_S1STAGE + arr * IN_S1ARR + (row * 72 + cc) * 2, gp);
        }
        asm volatile("cp.async.commit_group;");
    };

    float pacc[2][2][4];
    int total1 = tt * 12;
    issue1(0, 0, 0);
    for (int it = 0; it < total1; it++) {
        int s = it & 1;
        int kc = it % 12;
        if (kc == 0) {
#pragma unroll
            for (int i = 0; i < 2; i++)
#pragma unroll
                for (int q = 0; q < 2; q++)
#pragma unroll
                    for (int e = 0; e < 4; e++) pacc[i][q][e] = 0.0f;
        }
        if (it + 1 < total1) {
            issue1(1 - s, (it + 1) / 12, (it + 1) % 12);
            asm volatile("cp.async.wait_group 1;");
        } else {
            asm volatile("cp.async.wait_group 0;");
        }
        __syncthreads();

        uint32_t stg = STG + s * IN_S1STAGE;
#pragma unroll
        for (int kk = 0; kk < 4; kk++) {
            uint32_t ah[2][4], al[2][4];
#pragma unroll
            for (int mf = 0; mf < 2; mf++) {
                uint32_t addr = stg + ((wm * 32 + mf * 16 + (lane & 15)) * 72
                              + kk * 16 + (lane >> 4) * 8) * 2;
                ldsm_x4(ah[mf], addr);
                ldsm_x4(al[mf], addr + IN_S1ARR);
            }
            uint32_t bh[2][2], bl[2][2];
            {
                uint32_t addr = stg + 2 * IN_S1ARR
                              + ((wn * 16 + (lane & 7) + ((lane >> 4) << 3)) * 72
                              + kk * 16 + ((lane >> 3) & 1) * 8) * 2;
                uint32_t r[4];
                ldsm_x4(r, addr);
                bh[0][0] = r[0]; bh[0][1] = r[1]; bh[1][0] = r[2]; bh[1][1] = r[3];
                ldsm_x4(r, addr + IN_S1ARR);
                bl[0][0] = r[0]; bl[0][1] = r[1]; bl[1][0] = r[2]; bl[1][1] = r[3];
            }
#pragma unroll
            for (int mf = 0; mf < 2; mf++)
#pragma unroll
                for (int nf = 0; nf < 2; nf++) {
                    mma_bf16(pacc[mf][nf], ah[mf], bh[nf][0], bh[nf][1]);
                    mma_bf16(pacc[mf][nf], ah[mf], bl[nf][0], bl[nf][1]);
                    mma_bf16(pacc[mf][nf], al[mf], bh[nf][0], bh[nf][1]);
                }
        }

        if (kc == 11) {
            int j = it / 12;
#pragma unroll
            for (int mf = 0; mf < 2; mf++)
#pragma unroll
                for (int nf = 0; nf < 2; nf++) {
                    int row = wm * 32 + mf * 16 + gr;
                    int col = j * 64 + wn * 16 + nf * 8 + tig * 2;
#pragma unroll
                    for (int half = 0; half < 2; half++) {
                        __nv_bfloat162 lp;
                        __nv_bfloat162 hp = split_hi(pacc[mf][nf][half*2],
                                                     pacc[mf][nf][half*2+1], lp);
                        uint32_t off = ((row + half * 8) * IN_PSTRIDE + col) * 2;
                        *(__nv_bfloat162*)(sm + (Ph - smb) + off) = hp;
                        *(__nv_bfloat162*)(sm + (Pl - smb) + off) = lp;
                    }
                }
        }
        __syncthreads();
    }

    auto issue2 = [&](int s, int dt, int ec) {
#pragma unroll
        for (int q = 0; q < 8; q++) {
            int id = t + q * 256;
            int arr = id >> 10, rem = id & 1023;
            int row = rem >> 4, cc = (rem & 15) * 8;
            const __nv_bfloat16* gp = (arr == 0)
                ? g_Vsh + (krow0 + ec * 64 + row) * HD + dt * 128 + cc
                : g_Vsl + (krow0 + ec * 64 + row) * HD + dt * 128 + cc;
            cpasync16(STG + s * IN_S2STAGE + arr * IN_S2ARR + (row * 136 + cc) * 2, gp);
        }
        asm volatile("cp.async.commit_group;");
    };

    const float* sc = g_apow + ((size_t)tt * BB + b) * HD;
    float oacc[2][4][4];
    int total2 = 6 * tt;
    issue2(0, 0, 0);
    for (int it = 0; it < total2; it++) {
        int s = it & 1;
        int dt = it / tt, ec = it % tt;
        if (ec == 0) {
#pragma unroll
            for (int i = 0; i < 2; i++)
#pragma unroll
                for (int q = 0; q < 4; q++)
#pragma unroll
                    for (int e = 0; e < 4; e++) oacc[i][q][e] = 0.0f;
        }
        if (it + 1 < total2) {
            issue2(1 - s, (it + 1) / tt, (it + 1) % tt);
            asm volatile("cp.async.wait_group 1;");
        } else {
            asm volatile("cp.async.wait_group 0;");
        }
        __syncthreads();

        uint32_t stg = STG + s * IN_S2STAGE;
#pragma unroll
        for (int kk = 0; kk < 4; kk++) {
            uint32_t ah[2][4], al[2][4];
#pragma unroll
            for (int mf = 0; mf < 2; mf++) {
                uint32_t addr = Ph + ((wm * 32 + mf * 16 + (lane & 15)) * IN_PSTRIDE
                              + ec * 64 + kk * 16 + (lane >> 4) * 8) * 2;
                ldsm_x4(ah[mf], addr);
                ldsm_x4(al[mf], addr + IN_PBYTES);
            }
            uint32_t bh[4][2], bl[4][2];
#pragma unroll
            for (int ng = 0; ng < 2; ng++) {
                uint32_t addr = stg + ((kk * 16 + ((lane >> 3) & 1) * 8 + (lane & 7)) * 136
                              + wn * 32 + ng * 16 + (lane >> 4) * 8) * 2;
                uint32_t r[4];
                ldsm_x4_t(r, addr);
                bh[2*ng][0] = r[0]; bh[2*ng][1] = r[1];
                bh[2*ng+1][0] = r[2]; bh[2*ng+1][1] = r[3];
                ldsm_x4_t(r, addr + IN_S2ARR);
                bl[2*ng][0] = r[0]; bl[2*ng][1] = r[1];
                bl[2*ng+1][0] = r[2]; bl[2*ng+1][1] = r[3];
            }
#pragma unroll
            for (int mf = 0; mf < 2; mf++)
#pragma unroll
                for (int nf = 0; nf < 4; nf++) {
                    mma_bf16(oacc[mf][nf], ah[mf], bh[nf][0], bh[nf][1]);
                    mma_bf16(oacc[mf][nf], al[mf], bh[nf][0], bh[nf][1]);
                    mma_bf16(oacc[mf][nf], ah[mf], bl[nf][0], bl[nf][1]);
                }
        }

        if (ec == tt - 1) {
#pragma unroll
            for (int mf = 0; mf < 2; mf++) {
                size_t row = qrow0 + wm * 32 + mf * 16 + gr;
#pragma unroll
                for (int nf = 0; nf < 4; nf++) {
                    int col = dt * 128 + wn * 32 + nf * 8 + tig * 2;
                    float s0 = sc[col], s1 = sc[col + 1];
                    float* p0 = out + row * HD + col;
                    float* p1 = out + (row + 8) * HD + col;
                    float2 v0 = *(float2*)p0, v1 = *(float2*)p1;
                    v0.x += oacc[mf][nf][0] * s0; v0.y += oacc[mf][nf][1] * s1;
                    v1.x += oacc[mf][nf][2] * s0; v1.y += oacc[mf][nf][3] * s1;
                    *(float2*)p0 = v0; *(float2*)p1 = v1;
                }
            }
        }
        __syncthreads();
    }
}

// ================= launch =================
extern "C" void kernel_launch(void* const* d_in, const int* in_sizes, int n_in,
                              void* d_out, int out_size)
{
    const float* x  = (const float*)d_in[0];
    const float* Wq = (const float*)d_in[1];
    const float* Wk = (const float*)d_in[2];
    const float* Wv = (const float*)d_in[3];
    const float* W1 = (const float*)d_in[4];
    const float* W2 = (const float*)d_in[5];
    const float* bv = (const float*)d_in[6];
    float* out = (float*)d_out;

    cudaFuncSetAttribute((const void*)qkv_mma_kernel,
                         cudaFuncAttributeMaxDynamicSharedMemorySize, QKV_SMEM);
    cudaFuncSetAttribute((const void*)inter_kernel,
                         cudaFuncAttributeMaxDynamicSharedMemorySize, IT_SMEM);
    cudaFuncSetAttribute((const void*)chunk_total_kernel,
                         cudaFuncAttributeMaxDynamicSharedMemorySize, 69632);
    cudaFuncSetAttribute((const void*)intra_kernel,
                         cudaFuncAttributeMaxDynamicSharedMemorySize, IN_SMEM);
    cudaFuncSetAttribute((const void*)attn_mma_kernel,
                         cudaFuncAttributeMaxDynamicSharedMemorySize, AT_SMEM);
    cudaFuncSetAttribute((const void*)t16_kernel,
                         cudaFuncAttributeMaxDynamicSharedMemorySize, 52224);
    cudaFuncSetAttribute((const void*)sig_kernel,
                         cudaFuncAttributeMaxDynamicSharedMemorySize, 53248);

    convert_x_kernel<<<6144, 256>>>(x);
    convert_w_kernel<<<dim3(64, 1, 3), 256>>>(Wq, Wk, Wv);
    t16_kernel<<<4096, 256, 52224>>>(x, W1);
    sig_kernel<<<dim3(64, BB), 256, 53248>>>(W2, bv);
    powers_kernel<<<24, 256>>>();

    qkv_mma_kernel<<<dim3(6, 256, 3), 256, QKV_SMEM>>>();

    attn_mma_kernel<<<dim3(NBLK, BB), 256, AT_SMEM>>>(out);

    chunk_total_kernel<<<dim3(36, 56), 256, 69632>>>();
    scan_kernel<<<dim3(576, BB), 256>>>();
    inter_kernel<<<dim3(6, 4, 56), 256, IT_SMEM>>>(out);
    intra_kernel<<<dim3(7, 8, 8), 256, IN_SMEM>>>(out);
}